// round 7
// baseline (speedup 1.0000x reference)
#include <cuda_runtime.h>
#include <cuda_fp16.h>
#include <cstdint>
#include <math.h>

#define SS 256
#define NH 4
#define HD 32
#define DM 128
#define NROWS (SS*SS)   // 65536

// ---------------- scratch (device globals; no runtime alloc allowed) -------
__device__ float g_xn[(size_t)NROWS * DM];   // layernorm output      32MB
__device__ float g_bm[(size_t)NH * NROWS];   // bias+mask [H,S,S]      1MB
__device__ float g_q [(size_t)NROWS * DM];   // [S,H,S,DH]            32MB
__device__ float g_k [(size_t)NROWS * DM];
__device__ float g_v [(size_t)NROWS * DM];
__device__ float g_g [(size_t)NROWS * DM];   // gate proj [S,S,D]
__device__ float g_o [(size_t)NROWS * DM];   // attn out  [S,S,D]

// single extern shared symbol for the whole TU
extern __shared__ char smem_raw[];

__device__ __forceinline__ uint32_t f2tf32(float f) {
    uint32_t u;
    asm("cvt.rna.tf32.f32 %0, %1;" : "=r"(u) : "f"(f));
    return u;
}

// mma.sync m16n8k8 tf32 (sm_80+ PTX; valid on plain compute_103)
__device__ __forceinline__ void mma_tf32(float4& d,
                                         uint32_t a0, uint32_t a1, uint32_t a2, uint32_t a3,
                                         uint32_t b0, uint32_t b1) {
    asm volatile(
        "mma.sync.aligned.m16n8k8.row.col.f32.tf32.tf32.f32 "
        "{%0,%1,%2,%3}, {%4,%5,%6,%7}, {%8,%9}, {%0,%1,%2,%3};"
        : "+f"(d.x), "+f"(d.y), "+f"(d.z), "+f"(d.w)
        : "r"(a0), "r"(a1), "r"(a2), "r"(a3), "r"(b0), "r"(b1));
}

// mma.sync m16n8k16 fp16 with fp32 accumulate
__device__ __forceinline__ void mma_f16(float4& d,
                                        uint32_t a0, uint32_t a1, uint32_t a2, uint32_t a3,
                                        uint32_t b0, uint32_t b1) {
    asm volatile(
        "mma.sync.aligned.m16n8k16.row.col.f32.f16.f16.f32 "
        "{%0,%1,%2,%3}, {%4,%5,%6,%7}, {%8,%9}, {%0,%1,%2,%3};"
        : "+f"(d.x), "+f"(d.y), "+f"(d.z), "+f"(d.w)
        : "r"(a0), "r"(a1), "r"(a2), "r"(a3), "r"(b0), "r"(b1));
}

// pack two floats -> half2 in a b32 reg (lo in low half)
__device__ __forceinline__ uint32_t pack2h(float lo, float hi) {
    uint32_t r;
    asm("cvt.rn.f16x2.f32 %0, %1, %2;" : "=r"(r) : "f"(hi), "f"(lo));
    return r;
}
__device__ __forceinline__ float h2f_rn(float x) {   // fp16 round-trip
    return __half2float(__float2half_rn(x));
}

// ---------------- Kernel A: LayerNorm + (bias projection + mask) -----------
__global__ __launch_bounds__(256)
void ln_bias_kernel(const float* __restrict__ x,
                    const float* __restrict__ mask,
                    const float* __restrict__ lnw,
                    const float* __restrict__ lnb,
                    const float* __restrict__ Wb) {
    int lane = threadIdx.x & 31;
    int row  = blockIdx.x * 8 + (threadIdx.x >> 5);
    const float* xr = x + (size_t)row * DM;

    float v0 = xr[lane], v1 = xr[lane+32], v2 = xr[lane+64], v3 = xr[lane+96];
    float s = v0 + v1 + v2 + v3;
    #pragma unroll
    for (int o = 16; o; o >>= 1) s += __shfl_xor_sync(0xffffffffu, s, o);
    float mu = s * (1.0f/128.0f);
    float d0 = v0-mu, d1 = v1-mu, d2 = v2-mu, d3 = v3-mu;
    float qq = d0*d0 + d1*d1 + d2*d2 + d3*d3;
    #pragma unroll
    for (int o = 16; o; o >>= 1) qq += __shfl_xor_sync(0xffffffffu, qq, o);
    float inv = rsqrtf(qq * (1.0f/128.0f) + 1e-5f);

    float n0 = fmaf(d0*inv, lnw[lane   ], lnb[lane   ]);
    float n1 = fmaf(d1*inv, lnw[lane+32], lnb[lane+32]);
    float n2 = fmaf(d2*inv, lnw[lane+64], lnb[lane+64]);
    float n3 = fmaf(d3*inv, lnw[lane+96], lnb[lane+96]);

    float* xo = g_xn + (size_t)row * DM;
    xo[lane] = n0; xo[lane+32] = n1; xo[lane+64] = n2; xo[lane+96] = n3;

    float mval = mask[row];
    #pragma unroll
    for (int hh = 0; hh < NH; hh++) {
        const float* wb = Wb + hh * DM;
        float dot = n0*wb[lane] + n1*wb[lane+32] + n2*wb[lane+64] + n3*wb[lane+96];
        #pragma unroll
        for (int o = 16; o; o >>= 1) dot += __shfl_xor_sync(0xffffffffu, dot, o);
        if (lane == 0) g_bm[(size_t)hh * NROWS + row] = dot + mval;
    }
}

// ---------------- Kernel B: mma.sync tf32 GEMM ------------------------------
#define LDA 132
#define GEMM_SMEM (2 * 128 * LDA * 4)

__global__ __launch_bounds__(256, 1)
void gemm_tf32_kernel(const float* __restrict__ Wq, const float* __restrict__ Wk,
                      const float* __restrict__ Wv, const float* __restrict__ Wg,
                      const float* __restrict__ Wo, float* __restrict__ out, int mode) {
    uint32_t* As = (uint32_t*)smem_raw;        // [128][LDA] tf32
    uint32_t* Ws = As + 128 * LDA;             // [128][LDA] tf32

    int tid = threadIdx.x, wid = tid >> 5, lane = tid & 31;
    int m0 = blockIdx.x * 128;
    int lr = lane >> 2, lc = lane & 3;
    int wr = wid & 3;
    int wc = wid >> 2;

    if (mode == 0) {
        #pragma unroll
        for (int t = tid; t < 128 * 32; t += 256) {
            int row = t >> 5, c4 = (t & 31) * 4;
            float4 v = *(const float4*)(g_xn + (size_t)(m0 + row) * DM + c4);
            uint32_t* d = As + row * LDA + c4;
            d[0] = f2tf32(v.x); d[1] = f2tf32(v.y); d[2] = f2tf32(v.z); d[3] = f2tf32(v.w);
        }
    } else {
        #pragma unroll
        for (int t = tid; t < 128 * 32; t += 256) {
            int row = t >> 5, c4 = (t & 31) * 4;
            size_t gi = (size_t)(m0 + row) * DM + c4;
            float4 ov = *(const float4*)(g_o + gi);
            float4 gv = *(const float4*)(g_g + gi);
            uint32_t* d = As + row * LDA + c4;
            d[0] = f2tf32(ov.x / (1.0f + __expf(-gv.x)));
            d[1] = f2tf32(ov.y / (1.0f + __expf(-gv.y)));
            d[2] = f2tf32(ov.z / (1.0f + __expf(-gv.z)));
            d[3] = f2tf32(ov.w / (1.0f + __expf(-gv.w)));
        }
    }

    const float* Wsrc[4] = {Wq, Wk, Wv, Wg};
    int nW = (mode == 0) ? 4 : 1;

    for (int w = 0; w < nW; w++) {
        const float* W = (mode == 1) ? Wo : Wsrc[w];
        #pragma unroll
        for (int t = tid; t < 128 * 32; t += 256) {
            int row = t >> 5, c4 = (t & 31) * 4;
            float4 v = *(const float4*)(W + (size_t)row * DM + c4);
            uint32_t* d = Ws + row * LDA + c4;
            d[0] = f2tf32(v.x); d[1] = f2tf32(v.y); d[2] = f2tf32(v.z); d[3] = f2tf32(v.w);
        }
        __syncthreads();

        float4 acc[2][8];
        #pragma unroll
        for (int mt = 0; mt < 2; mt++)
            #pragma unroll
            for (int nt = 0; nt < 8; nt++) acc[mt][nt] = make_float4(0.f, 0.f, 0.f, 0.f);

        const uint32_t* Ab = As + (wr * 32 + lr) * LDA + lc;
        const uint32_t* Bb = Ws + (wc * 64 + lr) * LDA + lc;

        #pragma unroll
        for (int ks = 0; ks < 16; ks++) {
            int k0 = ks * 8;
            uint32_t a[2][4], b[8][2];
            #pragma unroll
            for (int mt = 0; mt < 2; mt++) {
                const uint32_t* p = Ab + mt * 16 * LDA + k0;
                a[mt][0] = p[0];
                a[mt][1] = p[8 * LDA];
                a[mt][2] = p[4];
                a[mt][3] = p[8 * LDA + 4];
            }
            #pragma unroll
            for (int nt = 0; nt < 8; nt++) {
                const uint32_t* p = Bb + nt * 8 * LDA + k0;
                b[nt][0] = p[0];
                b[nt][1] = p[4];
            }
            #pragma unroll
            for (int mt = 0; mt < 2; mt++)
                #pragma unroll
                for (int nt = 0; nt < 8; nt++)
                    mma_tf32(acc[mt][nt], a[mt][0], a[mt][1], a[mt][2], a[mt][3],
                             b[nt][0], b[nt][1]);
        }

        #pragma unroll
        for (int mt = 0; mt < 2; mt++) {
            int m = m0 + wr * 32 + mt * 16 + lr;
            #pragma unroll
            for (int nt = 0; nt < 8; nt++) {
                int e = wc * 64 + nt * 8 + 2 * lc;
                float2 lo = make_float2(acc[mt][nt].x, acc[mt][nt].y);
                float2 hi = make_float2(acc[mt][nt].z, acc[mt][nt].w);
                if (mode == 1) {
                    *(float2*)(out + (size_t)m * DM + e)       = lo;
                    *(float2*)(out + (size_t)(m + 8) * DM + e) = hi;
                } else if (w == 3) {
                    *(float2*)(g_g + (size_t)m * DM + e)       = lo;
                    *(float2*)(g_g + (size_t)(m + 8) * DM + e) = hi;
                } else {
                    float* dst3 = (w == 0) ? g_q : (w == 1) ? g_k : g_v;
                    int h = e >> 5, dh = e & 31;
                    int b0i = m >> 8, q0i = m & 255;
                    int b1i = (m + 8) >> 8, q1i = (m + 8) & 255;
                    *(float2*)(dst3 + (((size_t)(b0i * NH + h)) * SS + q0i) * HD + dh) = lo;
                    *(float2*)(dst3 + (((size_t)(b1i * NH + h)) * SS + q1i) * HD + dh) = hi;
                }
            }
        }
        __syncthreads();
    }
}

// ---------------- Kernel C: FA2 online-softmax fp16 split attention --------
// 512 threads, 16 warps; warp w owns q rows [w*16, w*16+16); keys in 2 chunks
// smem halves: Kh[256][40], Kl[256][40], Vh^T[32][264], Vl^T[32][264]
#define AT_KL 10240
#define AT_VH 20480
#define AT_VL 28928
#define ATTN_SMEM ((28928 + 8448) * 2)   // 74752 B

__global__ __launch_bounds__(512, 1)
void attn_fa_kernel() {
    __half* sh = (__half*)smem_raw;
    __half* Kh = sh;
    __half* Kl = sh + AT_KL;
    __half* Vh = sh + AT_VH;
    __half* Vl = sh + AT_VL;

    int bh = blockIdx.x, b = bh >> 2, h = bh & 3;
    const float* Qg = g_q + (size_t)bh * (SS * HD);
    const float* Kg = g_k + (size_t)bh * (SS * HD);
    const float* Vg = g_v + (size_t)bh * (SS * HD);

    int tid = threadIdx.x, warp = tid >> 5, lane = tid & 31;
    int lr = lane >> 2, lc = lane & 3;

    // ---- stage K hi/lo [key][dim] (stride 40) and V^T hi/lo [dim][key] (264)
    for (int i = tid; i < SS * HD; i += 512) {
        int key = i >> 5, d = i & 31;
        float kv = Kg[i];
        __half khv = __float2half_rn(kv);
        Kh[key * 40 + d] = khv;
        Kl[key * 40 + d] = __float2half_rn(kv - __half2float(khv));
        float vv = Vg[i];
        __half vhv = __float2half_rn(vv);
        Vh[d * 264 + key] = vhv;
        Vl[d * 264 + key] = __float2half_rn(vv - __half2float(vhv));
    }
    __syncthreads();

    const uint32_t* Khw = (const uint32_t*)Kh;   // word stride 20/row
    const uint32_t* Klw = (const uint32_t*)Kl;
    const uint32_t* Vhw = (const uint32_t*)Vh;   // word stride 132/row
    const uint32_t* Vlw = (const uint32_t*)Vl;

    int r0 = warp * 16 + lr;                     // rows r0 (.x/.y), r0+8 (.z/.w)

    // ---- Q fragments (pre-scaled, fp16 hi/lo split), loaded once ----
    uint32_t qh[2][4], ql[2][4];
    #pragma unroll
    for (int t = 0; t < 2; t++) {
        #pragma unroll
        for (int idx = 0; idx < 4; idx++) {
            int row = (idx & 1) ? r0 + 8 : r0;
            int dim = t * 16 + 2 * lc + ((idx >= 2) ? 8 : 0);
            float2 qv = *(const float2*)(Qg + (size_t)row * HD + dim);
            float qx = qv.x * 0.17677669529663687f;
            float qy = qv.y * 0.17677669529663687f;
            float hx = h2f_rn(qx), hy = h2f_rn(qy);
            qh[t][idx] = pack2h(hx, hy);
            ql[t][idx] = pack2h(qx - hx, qy - hy);
        }
    }

    // ---- online-softmax running state + output accumulators ----
    float m0r = -3.0e38f, m1r = -3.0e38f, l0 = 0.f, l1 = 0.f;
    float4 oacc[4];
    #pragma unroll
    for (int dn = 0; dn < 4; dn++) oacc[dn] = make_float4(0.f, 0.f, 0.f, 0.f);

    const float* bm0 = g_bm + (size_t)h * NROWS + (size_t)r0 * SS;
    const float* bm1 = bm0 + 8 * SS;

    #pragma unroll
    for (int c = 0; c < 2; c++) {
        // ---- S = Q K^T over this 128-key chunk (3-pass fp16 split) ----
        float4 acc[16];
        #pragma unroll
        for (int j = 0; j < 16; j++) acc[j] = make_float4(0.f, 0.f, 0.f, 0.f);

        #pragma unroll
        for (int j = 0; j < 16; j++) {
            int kw = (c * 128 + j * 8 + lr) * 20 + lc;
            uint32_t kh00 = Khw[kw],     kh01 = Khw[kw + 4];
            uint32_t kh10 = Khw[kw + 8], kh11 = Khw[kw + 12];
            uint32_t kl00 = Klw[kw],     kl01 = Klw[kw + 4];
            uint32_t kl10 = Klw[kw + 8], kl11 = Klw[kw + 12];
            mma_f16(acc[j], qh[0][0], qh[0][1], qh[0][2], qh[0][3], kh00, kh01);
            mma_f16(acc[j], qh[1][0], qh[1][1], qh[1][2], qh[1][3], kh10, kh11);
            mma_f16(acc[j], qh[0][0], qh[0][1], qh[0][2], qh[0][3], kl00, kl01);
            mma_f16(acc[j], qh[1][0], qh[1][1], qh[1][2], qh[1][3], kl10, kl11);
            mma_f16(acc[j], ql[0][0], ql[0][1], ql[0][2], ql[0][3], kh00, kh01);
            mma_f16(acc[j], ql[1][0], ql[1][1], ql[1][2], ql[1][3], kh10, kh11);
        }

        // ---- bias+mask add; chunk max (quad-local) ----
        float cx0 = -3.0e38f, cx1 = -3.0e38f;
        #pragma unroll
        for (int j = 0; j < 16; j++) {
            float2 b0 = *(const float2*)(bm0 + c * 128 + j * 8 + 2 * lc);
            float2 b1 = *(const float2*)(bm1 + c * 128 + j * 8 + 2 * lc);
            acc[j].x += b0.x; acc[j].y += b0.y;
            acc[j].z += b1.x; acc[j].w += b1.y;
            cx0 = fmaxf(cx0, fmaxf(acc[j].x, acc[j].y));
            cx1 = fmaxf(cx1, fmaxf(acc[j].z, acc[j].w));
        }
        cx0 = fmaxf(cx0, __shfl_xor_sync(0xffffffffu, cx0, 1));
        cx0 = fmaxf(cx0, __shfl_xor_sync(0xffffffffu, cx0, 2));
        cx1 = fmaxf(cx1, __shfl_xor_sync(0xffffffffu, cx1, 1));
        cx1 = fmaxf(cx1, __shfl_xor_sync(0xffffffffu, cx1, 2));

        // ---- online rescale ----
        float mn0 = fmaxf(m0r, cx0), mn1 = fmaxf(m1r, cx1);
        float al0 = __expf(m0r - mn0), al1 = __expf(m1r - mn1);
        m0r = mn0; m1r = mn1;
        l0 *= al0; l1 *= al1;
        #pragma unroll
        for (int dn = 0; dn < 4; dn++) {
            oacc[dn].x *= al0; oacc[dn].y *= al0;
            oacc[dn].z *= al1; oacc[dn].w *= al1;
        }

        // ---- exp + partial sums ----
        float s0 = 0.f, s1 = 0.f;
        #pragma unroll
        for (int j = 0; j < 16; j++) {
            acc[j].x = __expf(acc[j].x - mn0); s0 += acc[j].x;
            acc[j].y = __expf(acc[j].y - mn0); s0 += acc[j].y;
            acc[j].z = __expf(acc[j].z - mn1); s1 += acc[j].z;
            acc[j].w = __expf(acc[j].w - mn1); s1 += acc[j].w;
        }
        s0 += __shfl_xor_sync(0xffffffffu, s0, 1);
        s0 += __shfl_xor_sync(0xffffffffu, s0, 2);
        s1 += __shfl_xor_sync(0xffffffffu, s1, 1);
        s1 += __shfl_xor_sync(0xffffffffu, s1, 2);
        l0 += s0; l1 += s1;

        // ---- O += P V over chunk (3-pass), P from registers ----
        #pragma unroll
        for (int t = 0; t < 8; t++) {
            float4 c0 = acc[2 * t], c1 = acc[2 * t + 1];
            float h00 = h2f_rn(c0.x), h01 = h2f_rn(c0.y);
            float h02 = h2f_rn(c0.z), h03 = h2f_rn(c0.w);
            float h10 = h2f_rn(c1.x), h11 = h2f_rn(c1.y);
            float h12 = h2f_rn(c1.z), h13 = h2f_rn(c1.w);
            uint32_t ah0 = pack2h(h00, h01), ah1 = pack2h(h02, h03);
            uint32_t ah2 = pack2h(h10, h11), ah3 = pack2h(h12, h13);
            uint32_t al0w = pack2h(c0.x - h00, c0.y - h01);
            uint32_t al1w = pack2h(c0.z - h02, c0.w - h03);
            uint32_t al2w = pack2h(c1.x - h10, c1.y - h11);
            uint32_t al3w = pack2h(c1.z - h12, c1.w - h13);
            #pragma unroll
            for (int dn = 0; dn < 4; dn++) {
                int vw = (dn * 8 + lr) * 132 + c * 64 + 8 * t + lc;
                uint32_t vb0 = Vhw[vw], vb1 = Vhw[vw + 4];
                uint32_t wb0 = Vlw[vw], wb1 = Vlw[vw + 4];
                mma_f16(oacc[dn], ah0, ah1, ah2, ah3, vb0, vb1);
                mma_f16(oacc[dn], ah0, ah1, ah2, ah3, wb0, wb1);
                mma_f16(oacc[dn], al0w, al1w, al2w, al3w, vb0, vb1);
            }
        }
    }

    // ---- normalize + store ----
    float i0 = 1.0f / l0, i1 = 1.0f / l1;
    float* o0 = g_o + ((size_t)(b * 256 + r0) * NH + h) * HD;
    float* o1 = g_o + ((size_t)(b * 256 + r0 + 8) * NH + h) * HD;
    #pragma unroll
    for (int dn = 0; dn < 4; dn++) {
        *(float2*)(o0 + dn * 8 + 2 * lc) = make_float2(oacc[dn].x * i0, oacc[dn].y * i0);
        *(float2*)(o1 + dn * 8 + 2 * lc) = make_float2(oacc[dn].z * i1, oacc[dn].w * i1);
    }
}

// ---------------- launch ----------------------------------------------------
extern "C" void kernel_launch(void* const* d_in, const int* in_sizes, int n_in,
                              void* d_out, int out_size) {
    const float* x    = (const float*)d_in[0];
    const float* mask = (const float*)d_in[1];
    const float* lnw  = (const float*)d_in[2];
    const float* lnb  = (const float*)d_in[3];
    const float* Wb   = (const float*)d_in[4];
    const float* Wq   = (const float*)d_in[5];
    const float* Wk   = (const float*)d_in[6];
    const float* Wv   = (const float*)d_in[7];
    const float* Wg   = (const float*)d_in[8];
    const float* Wo   = (const float*)d_in[9];
    float* out = (float*)d_out;

    cudaFuncSetAttribute(gemm_tf32_kernel, cudaFuncAttributeMaxDynamicSharedMemorySize, GEMM_SMEM);
    cudaFuncSetAttribute(attn_fa_kernel,   cudaFuncAttributeMaxDynamicSharedMemorySize, ATTN_SMEM);

    ln_bias_kernel<<<NROWS / 8, 256>>>(x, mask, lnw, lnb, Wb);
    gemm_tf32_kernel<<<NROWS / 128, 256, GEMM_SMEM>>>(Wq, Wk, Wv, Wg, Wo, out, 0);
    attn_fa_kernel<<<SS * NH, 512, ATTN_SMEM>>>();
    gemm_tf32_kernel<<<NROWS / 128, 256, GEMM_SMEM>>>(Wq, Wk, Wv, Wg, Wo, out, 1);
}

// round 8
// speedup vs baseline: 1.2291x; 1.2291x over previous
#include <cuda_runtime.h>
#include <cuda_fp16.h>
#include <cstdint>
#include <math.h>

#define SS 256
#define NH 4
#define HD 32
#define DM 128
#define NROWS (SS*SS)   // 65536

// ---------------- scratch (device globals; no runtime alloc allowed) -------
__device__ float g_xn[(size_t)NROWS * DM];   // layernorm output      32MB
__device__ float g_bm[(size_t)NH * NROWS];   // bias+mask [H,S,S]      1MB
__device__ float g_q [(size_t)NROWS * DM];   // [S,H,S,DH]            32MB
__device__ float g_k [(size_t)NROWS * DM];
__device__ float g_v [(size_t)NROWS * DM];
__device__ float g_g [(size_t)NROWS * DM];   // gate proj [S,S,D]
__device__ float g_o [(size_t)NROWS * DM];   // attn out  [S,S,D]

// single extern shared symbol for the whole TU
extern __shared__ char smem_raw[];

__device__ __forceinline__ uint32_t f2tf32(float f) {
    uint32_t u;
    asm("cvt.rna.tf32.f32 %0, %1;" : "=r"(u) : "f"(f));
    return u;
}

// mma.sync m16n8k8 tf32 (sm_80+ PTX; valid on plain compute_103)
__device__ __forceinline__ void mma_tf32(float4& d,
                                         uint32_t a0, uint32_t a1, uint32_t a2, uint32_t a3,
                                         uint32_t b0, uint32_t b1) {
    asm volatile(
        "mma.sync.aligned.m16n8k8.row.col.f32.tf32.tf32.f32 "
        "{%0,%1,%2,%3}, {%4,%5,%6,%7}, {%8,%9}, {%0,%1,%2,%3};"
        : "+f"(d.x), "+f"(d.y), "+f"(d.z), "+f"(d.w)
        : "r"(a0), "r"(a1), "r"(a2), "r"(a3), "r"(b0), "r"(b1));
}

// mma.sync m16n8k16 fp16 with fp32 accumulate
__device__ __forceinline__ void mma_f16(float4& d,
                                        uint32_t a0, uint32_t a1, uint32_t a2, uint32_t a3,
                                        uint32_t b0, uint32_t b1) {
    asm volatile(
        "mma.sync.aligned.m16n8k16.row.col.f32.f16.f16.f32 "
        "{%0,%1,%2,%3}, {%4,%5,%6,%7}, {%8,%9}, {%0,%1,%2,%3};"
        : "+f"(d.x), "+f"(d.y), "+f"(d.z), "+f"(d.w)
        : "r"(a0), "r"(a1), "r"(a2), "r"(a3), "r"(b0), "r"(b1));
}

// pack two floats -> half2 in a b32 reg (lo in low half)
__device__ __forceinline__ uint32_t pack2h(float lo, float hi) {
    uint32_t r;
    asm("cvt.rn.f16x2.f32 %0, %1, %2;" : "=r"(r) : "f"(hi), "f"(lo));
    return r;
}
__device__ __forceinline__ float h2f_rn(float x) {   // fp16 round-trip
    return __half2float(__float2half_rn(x));
}

// ---------------- Kernel A: LayerNorm + (bias projection + mask) -----------
__global__ __launch_bounds__(256)
void ln_bias_kernel(const float* __restrict__ x,
                    const float* __restrict__ mask,
                    const float* __restrict__ lnw,
                    const float* __restrict__ lnb,
                    const float* __restrict__ Wb) {
    int lane = threadIdx.x & 31;
    int row  = blockIdx.x * 8 + (threadIdx.x >> 5);
    const float* xr = x + (size_t)row * DM;

    float v0 = xr[lane], v1 = xr[lane+32], v2 = xr[lane+64], v3 = xr[lane+96];
    float s = v0 + v1 + v2 + v3;
    #pragma unroll
    for (int o = 16; o; o >>= 1) s += __shfl_xor_sync(0xffffffffu, s, o);
    float mu = s * (1.0f/128.0f);
    float d0 = v0-mu, d1 = v1-mu, d2 = v2-mu, d3 = v3-mu;
    float qq = d0*d0 + d1*d1 + d2*d2 + d3*d3;
    #pragma unroll
    for (int o = 16; o; o >>= 1) qq += __shfl_xor_sync(0xffffffffu, qq, o);
    float inv = rsqrtf(qq * (1.0f/128.0f) + 1e-5f);

    float n0 = fmaf(d0*inv, lnw[lane   ], lnb[lane   ]);
    float n1 = fmaf(d1*inv, lnw[lane+32], lnb[lane+32]);
    float n2 = fmaf(d2*inv, lnw[lane+64], lnb[lane+64]);
    float n3 = fmaf(d3*inv, lnw[lane+96], lnb[lane+96]);

    float* xo = g_xn + (size_t)row * DM;
    xo[lane] = n0; xo[lane+32] = n1; xo[lane+64] = n2; xo[lane+96] = n3;

    float mval = mask[row];
    #pragma unroll
    for (int hh = 0; hh < NH; hh++) {
        const float* wb = Wb + hh * DM;
        float dot = n0*wb[lane] + n1*wb[lane+32] + n2*wb[lane+64] + n3*wb[lane+96];
        #pragma unroll
        for (int o = 16; o; o >>= 1) dot += __shfl_xor_sync(0xffffffffu, dot, o);
        if (lane == 0) g_bm[(size_t)hh * NROWS + row] = dot + mval;
    }
}

// ---------------- Kernel B: mma.sync tf32 GEMM, M-tile 64, 2 CTA/SM --------
#define LDA 132
#define GEMM_SMEM ((64 + 128) * LDA * 4)   // 101376 B

__global__ __launch_bounds__(256, 2)
void gemm_tf32_kernel(const float* __restrict__ Wq, const float* __restrict__ Wk,
                      const float* __restrict__ Wv, const float* __restrict__ Wg,
                      const float* __restrict__ Wo, float* __restrict__ out, int mode) {
    uint32_t* As = (uint32_t*)smem_raw;        // [64][LDA] tf32
    uint32_t* Ws = As + 64 * LDA;              // [128][LDA] tf32

    int tid = threadIdx.x, wid = tid >> 5, lane = tid & 31;
    int m0 = blockIdx.x * 64;
    int lr = lane >> 2, lc = lane & 3;
    int wr = wid & 1;          // M chunk of 32 (2 chunks)
    int wc = wid >> 1;         // N chunk of 32 (4 chunks)

    if (mode == 0) {
        #pragma unroll
        for (int t = tid; t < 64 * 32; t += 256) {
            int row = t >> 5, c4 = (t & 31) * 4;
            float4 v = *(const float4*)(g_xn + (size_t)(m0 + row) * DM + c4);
            uint32_t* d = As + row * LDA + c4;
            d[0] = f2tf32(v.x); d[1] = f2tf32(v.y); d[2] = f2tf32(v.z); d[3] = f2tf32(v.w);
        }
    } else {
        #pragma unroll
        for (int t = tid; t < 64 * 32; t += 256) {
            int row = t >> 5, c4 = (t & 31) * 4;
            size_t gi = (size_t)(m0 + row) * DM + c4;
            float4 ov = *(const float4*)(g_o + gi);
            float4 gv = *(const float4*)(g_g + gi);
            uint32_t* d = As + row * LDA + c4;
            d[0] = f2tf32(ov.x / (1.0f + __expf(-gv.x)));
            d[1] = f2tf32(ov.y / (1.0f + __expf(-gv.y)));
            d[2] = f2tf32(ov.z / (1.0f + __expf(-gv.z)));
            d[3] = f2tf32(ov.w / (1.0f + __expf(-gv.w)));
        }
    }

    const float* Wsrc[4] = {Wq, Wk, Wv, Wg};
    int nW = (mode == 0) ? 4 : 1;

    for (int w = 0; w < nW; w++) {
        const float* W = (mode == 1) ? Wo : Wsrc[w];
        #pragma unroll
        for (int t = tid; t < 128 * 32; t += 256) {
            int row = t >> 5, c4 = (t & 31) * 4;
            float4 v = *(const float4*)(W + (size_t)row * DM + c4);
            uint32_t* d = Ws + row * LDA + c4;
            d[0] = f2tf32(v.x); d[1] = f2tf32(v.y); d[2] = f2tf32(v.z); d[3] = f2tf32(v.w);
        }
        __syncthreads();

        float4 acc[2][4];
        #pragma unroll
        for (int mt = 0; mt < 2; mt++)
            #pragma unroll
            for (int nt = 0; nt < 4; nt++) acc[mt][nt] = make_float4(0.f, 0.f, 0.f, 0.f);

        const uint32_t* Ab = As + (wr * 32 + lr) * LDA + lc;
        const uint32_t* Bb = Ws + (wc * 32 + lr) * LDA + lc;

        #pragma unroll
        for (int ks = 0; ks < 16; ks++) {
            int k0 = ks * 8;
            uint32_t a[2][4], b[4][2];
            #pragma unroll
            for (int mt = 0; mt < 2; mt++) {
                const uint32_t* p = Ab + mt * 16 * LDA + k0;
                a[mt][0] = p[0];
                a[mt][1] = p[8 * LDA];
                a[mt][2] = p[4];
                a[mt][3] = p[8 * LDA + 4];
            }
            #pragma unroll
            for (int nt = 0; nt < 4; nt++) {
                const uint32_t* p = Bb + nt * 8 * LDA + k0;
                b[nt][0] = p[0];
                b[nt][1] = p[4];
            }
            #pragma unroll
            for (int mt = 0; mt < 2; mt++)
                #pragma unroll
                for (int nt = 0; nt < 4; nt++)
                    mma_tf32(acc[mt][nt], a[mt][0], a[mt][1], a[mt][2], a[mt][3],
                             b[nt][0], b[nt][1]);
        }

        #pragma unroll
        for (int mt = 0; mt < 2; mt++) {
            int m = m0 + wr * 32 + mt * 16 + lr;
            #pragma unroll
            for (int nt = 0; nt < 4; nt++) {
                int e = wc * 32 + nt * 8 + 2 * lc;
                float2 lo = make_float2(acc[mt][nt].x, acc[mt][nt].y);
                float2 hi = make_float2(acc[mt][nt].z, acc[mt][nt].w);
                if (mode == 1) {
                    *(float2*)(out + (size_t)m * DM + e)       = lo;
                    *(float2*)(out + (size_t)(m + 8) * DM + e) = hi;
                } else if (w == 3) {
                    *(float2*)(g_g + (size_t)m * DM + e)       = lo;
                    *(float2*)(g_g + (size_t)(m + 8) * DM + e) = hi;
                } else {
                    float* dst3 = (w == 0) ? g_q : (w == 1) ? g_k : g_v;
                    int h = e >> 5, dh = e & 31;
                    int b0i = m >> 8, q0i = m & 255;
                    int b1i = (m + 8) >> 8, q1i = (m + 8) & 255;
                    *(float2*)(dst3 + (((size_t)(b0i * NH + h)) * SS + q0i) * HD + dh) = lo;
                    *(float2*)(dst3 + (((size_t)(b1i * NH + h)) * SS + q1i) * HD + dh) = hi;
                }
            }
        }
        __syncthreads();
    }
}

// ---------------- Kernel C: FA2-style fp16 2-pass split attention ----------
// smem halves: Kh[256][40], Kl[256][40], Vh^T[32][264], Vl^T[32][264]
#define AT_KL 10240
#define AT_VH 20480
#define AT_VL 28928
#define ATTN_SMEM ((28928 + 8448) * 2)   // 74752 B

__global__ __launch_bounds__(256, 1)
void attn_fa_kernel() {
    __half* sh = (__half*)smem_raw;
    __half* Kh = sh;
    __half* Kl = sh + AT_KL;
    __half* Vh = sh + AT_VH;
    __half* Vl = sh + AT_VL;

    int bh = blockIdx.x, b = bh >> 2, h = bh & 3;
    const float* Qg = g_q + (size_t)bh * (SS * HD);
    const float* Kg = g_k + (size_t)bh * (SS * HD);
    const float* Vg = g_v + (size_t)bh * (SS * HD);

    int tid = threadIdx.x, warp = tid >> 5, lane = tid & 31;
    int lr = lane >> 2, lc = lane & 3;

    // ---- stage K hi/lo [key][dim] (stride 40) and V^T hi/lo [dim][key] (264)
    for (int i = tid; i < SS * HD; i += 256) {
        int key = i >> 5, d = i & 31;
        float kv = Kg[i];
        __half khv = __float2half_rn(kv);
        Kh[key * 40 + d] = khv;
        Kl[key * 40 + d] = __float2half_rn(kv - __half2float(khv));
        float vv = Vg[i];
        __half vhv = __float2half_rn(vv);
        Vh[d * 264 + key] = vhv;
        Vl[d * 264 + key] = __float2half_rn(vv - __half2float(vhv));
    }
    __syncthreads();

    const uint32_t* Khw = (const uint32_t*)Kh;   // word stride 20/row
    const uint32_t* Klw = (const uint32_t*)Kl;
    const uint32_t* Vhw = (const uint32_t*)Vh;   // word stride 132/row
    const uint32_t* Vlw = (const uint32_t*)Vl;

    for (int qt = 0; qt < 2; qt++) {
        int r0 = qt * 128 + warp * 16 + lr;      // rows r0 (.x/.y) and r0+8 (.z/.w)

        // ---- Q fragments (pre-scaled, fp16 hi used; residual folded into hi
        //      via 2-pass with K residual) ----
        uint32_t qh[2][4];
        #pragma unroll
        for (int t = 0; t < 2; t++) {
            #pragma unroll
            for (int idx = 0; idx < 4; idx++) {
                int row = (idx & 1) ? r0 + 8 : r0;
                int dim = t * 16 + 2 * lc + ((idx >= 2) ? 8 : 0);
                float2 qv = *(const float2*)(Qg + (size_t)row * HD + dim);
                float qx = qv.x * 0.17677669529663687f;
                float qy = qv.y * 0.17677669529663687f;
                qh[t][idx] = pack2h(h2f_rn(qx), h2f_rn(qy));
            }
        }

        // ---- S = Q K^T : 2-pass fp16 (qh*kh + qh*kl) ----
        float4 acc[32];
        #pragma unroll
        for (int j = 0; j < 32; j++) acc[j] = make_float4(0.f, 0.f, 0.f, 0.f);

        #pragma unroll
        for (int j = 0; j < 32; j++) {
            int kw = (j * 8 + lr) * 20 + lc;
            uint32_t kh00 = Khw[kw],     kh01 = Khw[kw + 4];
            uint32_t kh10 = Khw[kw + 8], kh11 = Khw[kw + 12];
            uint32_t kl00 = Klw[kw],     kl01 = Klw[kw + 4];
            uint32_t kl10 = Klw[kw + 8], kl11 = Klw[kw + 12];
            mma_f16(acc[j], qh[0][0], qh[0][1], qh[0][2], qh[0][3], kh00, kh01);
            mma_f16(acc[j], qh[1][0], qh[1][1], qh[1][2], qh[1][3], kh10, kh11);
            mma_f16(acc[j], qh[0][0], qh[0][1], qh[0][2], qh[0][3], kl00, kl01);
            mma_f16(acc[j], qh[1][0], qh[1][1], qh[1][2], qh[1][3], kl10, kl11);
        }

        // ---- bias+mask add, softmax over 256 cols (quad-local reduction) ---
        const float* bm0 = g_bm + (size_t)h * NROWS + (size_t)r0 * SS;
        const float* bm1 = bm0 + 8 * SS;
        float mx0 = -3.0e38f, mx1 = -3.0e38f;
        #pragma unroll
        for (int j = 0; j < 32; j++) {
            float2 b0 = *(const float2*)(bm0 + j * 8 + 2 * lc);
            float2 b1 = *(const float2*)(bm1 + j * 8 + 2 * lc);
            acc[j].x += b0.x; acc[j].y += b0.y;
            acc[j].z += b1.x; acc[j].w += b1.y;
            mx0 = fmaxf(mx0, fmaxf(acc[j].x, acc[j].y));
            mx1 = fmaxf(mx1, fmaxf(acc[j].z, acc[j].w));
        }
        mx0 = fmaxf(mx0, __shfl_xor_sync(0xffffffffu, mx0, 1));
        mx0 = fmaxf(mx0, __shfl_xor_sync(0xffffffffu, mx0, 2));
        mx1 = fmaxf(mx1, __shfl_xor_sync(0xffffffffu, mx1, 1));
        mx1 = fmaxf(mx1, __shfl_xor_sync(0xffffffffu, mx1, 2));
        float s0 = 0.f, s1 = 0.f;
        #pragma unroll
        for (int j = 0; j < 32; j++) {
            acc[j].x = __expf(acc[j].x - mx0); s0 += acc[j].x;
            acc[j].y = __expf(acc[j].y - mx0); s0 += acc[j].y;
            acc[j].z = __expf(acc[j].z - mx1); s1 += acc[j].z;
            acc[j].w = __expf(acc[j].w - mx1); s1 += acc[j].w;
        }
        s0 += __shfl_xor_sync(0xffffffffu, s0, 1);
        s0 += __shfl_xor_sync(0xffffffffu, s0, 2);
        s1 += __shfl_xor_sync(0xffffffffu, s1, 1);
        s1 += __shfl_xor_sync(0xffffffffu, s1, 2);
        float i0 = 1.0f / s0, i1 = 1.0f / s1;
        #pragma unroll
        for (int j = 0; j < 32; j++) {
            acc[j].x *= i0; acc[j].y *= i0; acc[j].z *= i1; acc[j].w *= i1;
        }

        // ---- O = P V : 2-pass (ph*vh + ph*vl), P from registers ----
        float4 oacc[4];
        #pragma unroll
        for (int dn = 0; dn < 4; dn++) oacc[dn] = make_float4(0.f, 0.f, 0.f, 0.f);

        #pragma unroll
        for (int t = 0; t < 16; t++) {
            float4 c0 = acc[2 * t], c1 = acc[2 * t + 1];
            uint32_t ah0 = pack2h(h2f_rn(c0.x), h2f_rn(c0.y));
            uint32_t ah1 = pack2h(h2f_rn(c0.z), h2f_rn(c0.w));
            uint32_t ah2 = pack2h(h2f_rn(c1.x), h2f_rn(c1.y));
            uint32_t ah3 = pack2h(h2f_rn(c1.z), h2f_rn(c1.w));
            #pragma unroll
            for (int dn = 0; dn < 4; dn++) {
                int vw = (dn * 8 + lr) * 132 + 8 * t + lc;
                uint32_t vb0 = Vhw[vw], vb1 = Vhw[vw + 4];
                uint32_t wb0 = Vlw[vw], wb1 = Vlw[vw + 4];
                mma_f16(oacc[dn], ah0, ah1, ah2, ah3, vb0, vb1);
                mma_f16(oacc[dn], ah0, ah1, ah2, ah3, wb0, wb1);
            }
        }

        // ---- store O: rows r0, r0+8; dims dn*8 + 2lc,+1 ----
        float* o0 = g_o + ((size_t)(b * 256 + r0) * NH + h) * HD;
        float* o1 = g_o + ((size_t)(b * 256 + r0 + 8) * NH + h) * HD;
        #pragma unroll
        for (int dn = 0; dn < 4; dn++) {
            *(float2*)(o0 + dn * 8 + 2 * lc) = make_float2(oacc[dn].x, oacc[dn].y);
            *(float2*)(o1 + dn * 8 + 2 * lc) = make_float2(oacc[dn].z, oacc[dn].w);
        }
    }
}

// ---------------- launch ----------------------------------------------------
extern "C" void kernel_launch(void* const* d_in, const int* in_sizes, int n_in,
                              void* d_out, int out_size) {
    const float* x    = (const float*)d_in[0];
    const float* mask = (const float*)d_in[1];
    const float* lnw  = (const float*)d_in[2];
    const float* lnb  = (const float*)d_in[3];
    const float* Wb   = (const float*)d_in[4];
    const float* Wq   = (const float*)d_in[5];
    const float* Wk   = (const float*)d_in[6];
    const float* Wv   = (const float*)d_in[7];
    const float* Wg   = (const float*)d_in[8];
    const float* Wo   = (const float*)d_in[9];
    float* out = (float*)d_out;

    cudaFuncSetAttribute(gemm_tf32_kernel, cudaFuncAttributeMaxDynamicSharedMemorySize, GEMM_SMEM);
    cudaFuncSetAttribute(attn_fa_kernel,   cudaFuncAttributeMaxDynamicSharedMemorySize, ATTN_SMEM);

    ln_bias_kernel<<<NROWS / 8, 256>>>(x, mask, lnw, lnb, Wb);
    gemm_tf32_kernel<<<NROWS / 64, 256, GEMM_SMEM>>>(Wq, Wk, Wv, Wg, Wo, out, 0);
    attn_fa_kernel<<<SS * NH, 256, ATTN_SMEM>>>();
    gemm_tf32_kernel<<<NROWS / 64, 256, GEMM_SMEM>>>(Wq, Wk, Wv, Wg, Wo, out, 1);
}

// round 9
// speedup vs baseline: 1.3868x; 1.1284x over previous
#include <cuda_runtime.h>
#include <cuda_fp16.h>
#include <cstdint>
#include <math.h>

#define SS 256
#define NH 4
#define HD 32
#define DM 128
#define NROWS (SS*SS)   // 65536

// ---------------- scratch (device globals; no runtime alloc allowed) -------
__device__ float g_xn[(size_t)NROWS * DM];   // layernorm output      32MB
__device__ float g_bm[(size_t)NH * NROWS];   // bias+mask [H,S,S]      1MB
__device__ float g_q [(size_t)NROWS * DM];   // [S,H,S,DH]            32MB
__device__ float g_k [(size_t)NROWS * DM];
__device__ float g_v [(size_t)NROWS * DM];
__device__ float g_g [(size_t)NROWS * DM];   // gate proj [S,S,D]
__device__ float g_o [(size_t)NROWS * DM];   // attn out  [S,S,D]

// single extern shared symbol for the whole TU
extern __shared__ char smem_raw[];

__device__ __forceinline__ uint32_t f2tf32(float f) {
    uint32_t u;
    asm("cvt.rna.tf32.f32 %0, %1;" : "=r"(u) : "f"(f));
    return u;
}

// mma.sync m16n8k8 tf32 (sm_80+ PTX; valid on plain compute_103)
__device__ __forceinline__ void mma_tf32(float4& d,
                                         uint32_t a0, uint32_t a1, uint32_t a2, uint32_t a3,
                                         uint32_t b0, uint32_t b1) {
    asm volatile(
        "mma.sync.aligned.m16n8k8.row.col.f32.tf32.tf32.f32 "
        "{%0,%1,%2,%3}, {%4,%5,%6,%7}, {%8,%9}, {%0,%1,%2,%3};"
        : "+f"(d.x), "+f"(d.y), "+f"(d.z), "+f"(d.w)
        : "r"(a0), "r"(a1), "r"(a2), "r"(a3), "r"(b0), "r"(b1));
}

// mma.sync m16n8k16 fp16 with fp32 accumulate
__device__ __forceinline__ void mma_f16(float4& d,
                                        uint32_t a0, uint32_t a1, uint32_t a2, uint32_t a3,
                                        uint32_t b0, uint32_t b1) {
    asm volatile(
        "mma.sync.aligned.m16n8k16.row.col.f32.f16.f16.f32 "
        "{%0,%1,%2,%3}, {%4,%5,%6,%7}, {%8,%9}, {%0,%1,%2,%3};"
        : "+f"(d.x), "+f"(d.y), "+f"(d.z), "+f"(d.w)
        : "r"(a0), "r"(a1), "r"(a2), "r"(a3), "r"(b0), "r"(b1));
}

// pack two floats -> half2 in a b32 reg (lo in low half)
__device__ __forceinline__ uint32_t pack2h(float lo, float hi) {
    uint32_t r;
    asm("cvt.rn.f16x2.f32 %0, %1, %2;" : "=r"(r) : "f"(hi), "f"(lo));
    return r;
}
__device__ __forceinline__ float h2f_rn(float x) {   // fp16 round-trip
    return __half2float(__float2half_rn(x));
}

// ---------------- Kernel A: LayerNorm + (bias projection + mask) -----------
__global__ __launch_bounds__(256)
void ln_bias_kernel(const float* __restrict__ x,
                    const float* __restrict__ mask,
                    const float* __restrict__ lnw,
                    const float* __restrict__ lnb,
                    const float* __restrict__ Wb) {
    int lane = threadIdx.x & 31;
    int row  = blockIdx.x * 8 + (threadIdx.x >> 5);
    const float* xr = x + (size_t)row * DM;

    float v0 = xr[lane], v1 = xr[lane+32], v2 = xr[lane+64], v3 = xr[lane+96];
    float s = v0 + v1 + v2 + v3;
    #pragma unroll
    for (int o = 16; o; o >>= 1) s += __shfl_xor_sync(0xffffffffu, s, o);
    float mu = s * (1.0f/128.0f);
    float d0 = v0-mu, d1 = v1-mu, d2 = v2-mu, d3 = v3-mu;
    float qq = d0*d0 + d1*d1 + d2*d2 + d3*d3;
    #pragma unroll
    for (int o = 16; o; o >>= 1) qq += __shfl_xor_sync(0xffffffffu, qq, o);
    float inv = rsqrtf(qq * (1.0f/128.0f) + 1e-5f);

    float n0 = fmaf(d0*inv, lnw[lane   ], lnb[lane   ]);
    float n1 = fmaf(d1*inv, lnw[lane+32], lnb[lane+32]);
    float n2 = fmaf(d2*inv, lnw[lane+64], lnb[lane+64]);
    float n3 = fmaf(d3*inv, lnw[lane+96], lnb[lane+96]);

    float* xo = g_xn + (size_t)row * DM;
    xo[lane] = n0; xo[lane+32] = n1; xo[lane+64] = n2; xo[lane+96] = n3;

    float mval = mask[row];
    #pragma unroll
    for (int hh = 0; hh < NH; hh++) {
        const float* wb = Wb + hh * DM;
        float dot = n0*wb[lane] + n1*wb[lane+32] + n2*wb[lane+64] + n3*wb[lane+96];
        #pragma unroll
        for (int o = 16; o; o >>= 1) dot += __shfl_xor_sync(0xffffffffu, dot, o);
        if (lane == 0) g_bm[(size_t)hh * NROWS + row] = dot + mval;
    }
}

// ---------------- Kernel B: mma.sync tf32 GEMM, M-tile 64, 2 CTA/SM --------
#define LDA 132
#define GEMM_SMEM ((64 + 128) * LDA * 4)   // 101376 B

__global__ __launch_bounds__(256, 2)
void gemm_tf32_kernel(const float* __restrict__ Wq, const float* __restrict__ Wk,
                      const float* __restrict__ Wv, const float* __restrict__ Wg,
                      const float* __restrict__ Wo, float* __restrict__ out, int mode) {
    uint32_t* As = (uint32_t*)smem_raw;        // [64][LDA] tf32
    uint32_t* Ws = As + 64 * LDA;              // [128][LDA] tf32

    int tid = threadIdx.x, wid = tid >> 5, lane = tid & 31;
    int m0 = blockIdx.x * 64;
    int lr = lane >> 2, lc = lane & 3;
    int wr = wid & 1;          // M chunk of 32 (2 chunks)
    int wc = wid >> 1;         // N chunk of 32 (4 chunks)

    if (mode == 0) {
        #pragma unroll
        for (int t = tid; t < 64 * 32; t += 256) {
            int row = t >> 5, c4 = (t & 31) * 4;
            float4 v = *(const float4*)(g_xn + (size_t)(m0 + row) * DM + c4);
            uint32_t* d = As + row * LDA + c4;
            d[0] = f2tf32(v.x); d[1] = f2tf32(v.y); d[2] = f2tf32(v.z); d[3] = f2tf32(v.w);
        }
    } else {
        #pragma unroll
        for (int t = tid; t < 64 * 32; t += 256) {
            int row = t >> 5, c4 = (t & 31) * 4;
            size_t gi = (size_t)(m0 + row) * DM + c4;
            float4 ov = *(const float4*)(g_o + gi);
            float4 gv = *(const float4*)(g_g + gi);
            uint32_t* d = As + row * LDA + c4;
            d[0] = f2tf32(ov.x / (1.0f + __expf(-gv.x)));
            d[1] = f2tf32(ov.y / (1.0f + __expf(-gv.y)));
            d[2] = f2tf32(ov.z / (1.0f + __expf(-gv.z)));
            d[3] = f2tf32(ov.w / (1.0f + __expf(-gv.w)));
        }
    }

    const float* Wsrc[4] = {Wq, Wk, Wv, Wg};
    int nW = (mode == 0) ? 4 : 1;

    for (int w = 0; w < nW; w++) {
        const float* W = (mode == 1) ? Wo : Wsrc[w];
        #pragma unroll
        for (int t = tid; t < 128 * 32; t += 256) {
            int row = t >> 5, c4 = (t & 31) * 4;
            float4 v = *(const float4*)(W + (size_t)row * DM + c4);
            uint32_t* d = Ws + row * LDA + c4;
            d[0] = f2tf32(v.x); d[1] = f2tf32(v.y); d[2] = f2tf32(v.z); d[3] = f2tf32(v.w);
        }
        __syncthreads();

        float4 acc[2][4];
        #pragma unroll
        for (int mt = 0; mt < 2; mt++)
            #pragma unroll
            for (int nt = 0; nt < 4; nt++) acc[mt][nt] = make_float4(0.f, 0.f, 0.f, 0.f);

        const uint32_t* Ab = As + (wr * 32 + lr) * LDA + lc;
        const uint32_t* Bb = Ws + (wc * 32 + lr) * LDA + lc;

        #pragma unroll
        for (int ks = 0; ks < 16; ks++) {
            int k0 = ks * 8;
            uint32_t a[2][4], b[4][2];
            #pragma unroll
            for (int mt = 0; mt < 2; mt++) {
                const uint32_t* p = Ab + mt * 16 * LDA + k0;
                a[mt][0] = p[0];
                a[mt][1] = p[8 * LDA];
                a[mt][2] = p[4];
                a[mt][3] = p[8 * LDA + 4];
            }
            #pragma unroll
            for (int nt = 0; nt < 4; nt++) {
                const uint32_t* p = Bb + nt * 8 * LDA + k0;
                b[nt][0] = p[0];
                b[nt][1] = p[4];
            }
            #pragma unroll
            for (int mt = 0; mt < 2; mt++)
                #pragma unroll
                for (int nt = 0; nt < 4; nt++)
                    mma_tf32(acc[mt][nt], a[mt][0], a[mt][1], a[mt][2], a[mt][3],
                             b[nt][0], b[nt][1]);
        }

        #pragma unroll
        for (int mt = 0; mt < 2; mt++) {
            int m = m0 + wr * 32 + mt * 16 + lr;
            #pragma unroll
            for (int nt = 0; nt < 4; nt++) {
                int e = wc * 32 + nt * 8 + 2 * lc;
                float2 lo = make_float2(acc[mt][nt].x, acc[mt][nt].y);
                float2 hi = make_float2(acc[mt][nt].z, acc[mt][nt].w);
                if (mode == 1) {
                    *(float2*)(out + (size_t)m * DM + e)       = lo;
                    *(float2*)(out + (size_t)(m + 8) * DM + e) = hi;
                } else if (w == 3) {
                    *(float2*)(g_g + (size_t)m * DM + e)       = lo;
                    *(float2*)(g_g + (size_t)(m + 8) * DM + e) = hi;
                } else {
                    float* dst3 = (w == 0) ? g_q : (w == 1) ? g_k : g_v;
                    int h = e >> 5, dh = e & 31;
                    int b0i = m >> 8, q0i = m & 255;
                    int b1i = (m + 8) >> 8, q1i = (m + 8) & 255;
                    *(float2*)(dst3 + (((size_t)(b0i * NH + h)) * SS + q0i) * HD + dh) = lo;
                    *(float2*)(dst3 + (((size_t)(b1i * NH + h)) * SS + q1i) * HD + dh) = hi;
                }
            }
        }
        __syncthreads();
    }
}

// ---------------- Kernel C: FA2 fp16 2-pass attention, 2 CTA/SM ------------
// 8 warps; online softmax over 2 key chunks of 128 -> acc[16] (64 regs)
// smem halves: Kh[256][40], Kl[256][40], Vh^T[32][264], Vl^T[32][264]
#define AT_KL 10240
#define AT_VH 20480
#define AT_VL 28928
#define ATTN_SMEM ((28928 + 8448) * 2)   // 74752 B

__global__ __launch_bounds__(256, 2)
void attn_fa_kernel() {
    __half* sh = (__half*)smem_raw;
    __half* Kh = sh;
    __half* Kl = sh + AT_KL;
    __half* Vh = sh + AT_VH;
    __half* Vl = sh + AT_VL;

    int bh = blockIdx.x, b = bh >> 2, h = bh & 3;
    const float* Qg = g_q + (size_t)bh * (SS * HD);
    const float* Kg = g_k + (size_t)bh * (SS * HD);
    const float* Vg = g_v + (size_t)bh * (SS * HD);

    int tid = threadIdx.x, warp = tid >> 5, lane = tid & 31;
    int lr = lane >> 2, lc = lane & 3;

    // ---- stage K hi/lo [key][dim] (stride 40) and V^T hi/lo [dim][key] (264)
    for (int i = tid; i < SS * HD; i += 256) {
        int key = i >> 5, d = i & 31;
        float kv = Kg[i];
        __half khv = __float2half_rn(kv);
        Kh[key * 40 + d] = khv;
        Kl[key * 40 + d] = __float2half_rn(kv - __half2float(khv));
        float vv = Vg[i];
        __half vhv = __float2half_rn(vv);
        Vh[d * 264 + key] = vhv;
        Vl[d * 264 + key] = __float2half_rn(vv - __half2float(vhv));
    }
    __syncthreads();

    const uint32_t* Khw = (const uint32_t*)Kh;   // word stride 20/row
    const uint32_t* Klw = (const uint32_t*)Kl;
    const uint32_t* Vhw = (const uint32_t*)Vh;   // word stride 132/row
    const uint32_t* Vlw = (const uint32_t*)Vl;

    for (int qt = 0; qt < 2; qt++) {
        int r0 = qt * 128 + warp * 16 + lr;      // rows r0 (.x/.y) and r0+8 (.z/.w)

        // ---- Q fragments (pre-scaled, fp16 hi; 2-pass compensates via Kl) --
        uint32_t qh[2][4];
        #pragma unroll
        for (int t = 0; t < 2; t++) {
            #pragma unroll
            for (int idx = 0; idx < 4; idx++) {
                int row = (idx & 1) ? r0 + 8 : r0;
                int dim = t * 16 + 2 * lc + ((idx >= 2) ? 8 : 0);
                float2 qv = *(const float2*)(Qg + (size_t)row * HD + dim);
                float qx = qv.x * 0.17677669529663687f;
                float qy = qv.y * 0.17677669529663687f;
                qh[t][idx] = pack2h(h2f_rn(qx), h2f_rn(qy));
            }
        }

        const float* bm0 = g_bm + (size_t)h * NROWS + (size_t)r0 * SS;
        const float* bm1 = bm0 + 8 * SS;

        // ---- online-softmax state + output accumulators ----
        float m0r = -3.0e38f, m1r = -3.0e38f, l0 = 0.f, l1 = 0.f;
        float4 oacc[4];
        #pragma unroll
        for (int dn = 0; dn < 4; dn++) oacc[dn] = make_float4(0.f, 0.f, 0.f, 0.f);

        #pragma unroll
        for (int c = 0; c < 2; c++) {
            // ---- S = Q K^T over this 128-key chunk (2-pass: qh*kh + qh*kl) -
            float4 acc[16];
            #pragma unroll
            for (int j = 0; j < 16; j++) acc[j] = make_float4(0.f, 0.f, 0.f, 0.f);

            #pragma unroll
            for (int j = 0; j < 16; j++) {
                int kw = (c * 128 + j * 8 + lr) * 20 + lc;
                uint32_t kh00 = Khw[kw],     kh01 = Khw[kw + 4];
                uint32_t kh10 = Khw[kw + 8], kh11 = Khw[kw + 12];
                uint32_t kl00 = Klw[kw],     kl01 = Klw[kw + 4];
                uint32_t kl10 = Klw[kw + 8], kl11 = Klw[kw + 12];
                mma_f16(acc[j], qh[0][0], qh[0][1], qh[0][2], qh[0][3], kh00, kh01);
                mma_f16(acc[j], qh[1][0], qh[1][1], qh[1][2], qh[1][3], kh10, kh11);
                mma_f16(acc[j], qh[0][0], qh[0][1], qh[0][2], qh[0][3], kl00, kl01);
                mma_f16(acc[j], qh[1][0], qh[1][1], qh[1][2], qh[1][3], kl10, kl11);
            }

            // ---- bias+mask add; chunk max (quad-local) ----
            float cx0 = -3.0e38f, cx1 = -3.0e38f;
            #pragma unroll
            for (int j = 0; j < 16; j++) {
                float2 b0 = *(const float2*)(bm0 + c * 128 + j * 8 + 2 * lc);
                float2 b1 = *(const float2*)(bm1 + c * 128 + j * 8 + 2 * lc);
                acc[j].x += b0.x; acc[j].y += b0.y;
                acc[j].z += b1.x; acc[j].w += b1.y;
                cx0 = fmaxf(cx0, fmaxf(acc[j].x, acc[j].y));
                cx1 = fmaxf(cx1, fmaxf(acc[j].z, acc[j].w));
            }
            cx0 = fmaxf(cx0, __shfl_xor_sync(0xffffffffu, cx0, 1));
            cx0 = fmaxf(cx0, __shfl_xor_sync(0xffffffffu, cx0, 2));
            cx1 = fmaxf(cx1, __shfl_xor_sync(0xffffffffu, cx1, 1));
            cx1 = fmaxf(cx1, __shfl_xor_sync(0xffffffffu, cx1, 2));

            // ---- online rescale ----
            float mn0 = fmaxf(m0r, cx0), mn1 = fmaxf(m1r, cx1);
            float al0 = __expf(m0r - mn0), al1 = __expf(m1r - mn1);
            m0r = mn0; m1r = mn1;
            l0 *= al0; l1 *= al1;
            #pragma unroll
            for (int dn = 0; dn < 4; dn++) {
                oacc[dn].x *= al0; oacc[dn].y *= al0;
                oacc[dn].z *= al1; oacc[dn].w *= al1;
            }

            // ---- exp + partial sums ----
            float s0 = 0.f, s1 = 0.f;
            #pragma unroll
            for (int j = 0; j < 16; j++) {
                acc[j].x = __expf(acc[j].x - mn0); s0 += acc[j].x;
                acc[j].y = __expf(acc[j].y - mn0); s0 += acc[j].y;
                acc[j].z = __expf(acc[j].z - mn1); s1 += acc[j].z;
                acc[j].w = __expf(acc[j].w - mn1); s1 += acc[j].w;
            }
            s0 += __shfl_xor_sync(0xffffffffu, s0, 1);
            s0 += __shfl_xor_sync(0xffffffffu, s0, 2);
            s1 += __shfl_xor_sync(0xffffffffu, s1, 1);
            s1 += __shfl_xor_sync(0xffffffffu, s1, 2);
            l0 += s0; l1 += s1;

            // ---- O += P V over chunk (2-pass: ph*vh + ph*vl) ----
            #pragma unroll
            for (int t = 0; t < 8; t++) {
                float4 c0 = acc[2 * t], c1 = acc[2 * t + 1];
                uint32_t ah0 = pack2h(h2f_rn(c0.x), h2f_rn(c0.y));
                uint32_t ah1 = pack2h(h2f_rn(c0.z), h2f_rn(c0.w));
                uint32_t ah2 = pack2h(h2f_rn(c1.x), h2f_rn(c1.y));
                uint32_t ah3 = pack2h(h2f_rn(c1.z), h2f_rn(c1.w));
                #pragma unroll
                for (int dn = 0; dn < 4; dn++) {
                    int vw = (dn * 8 + lr) * 132 + c * 64 + 8 * t + lc;
                    uint32_t vb0 = Vhw[vw], vb1 = Vhw[vw + 4];
                    uint32_t wb0 = Vlw[vw], wb1 = Vlw[vw + 4];
                    mma_f16(oacc[dn], ah0, ah1, ah2, ah3, vb0, vb1);
                    mma_f16(oacc[dn], ah0, ah1, ah2, ah3, wb0, wb1);
                }
            }
        }

        // ---- normalize + store ----
        float i0 = 1.0f / l0, i1 = 1.0f / l1;
        float* o0 = g_o + ((size_t)(b * 256 + r0) * NH + h) * HD;
        float* o1 = g_o + ((size_t)(b * 256 + r0 + 8) * NH + h) * HD;
        #pragma unroll
        for (int dn = 0; dn < 4; dn++) {
            *(float2*)(o0 + dn * 8 + 2 * lc) = make_float2(oacc[dn].x * i0, oacc[dn].y * i0);
            *(float2*)(o1 + dn * 8 + 2 * lc) = make_float2(oacc[dn].z * i1, oacc[dn].w * i1);
        }
    }
}

// ---------------- launch ----------------------------------------------------
extern "C" void kernel_launch(void* const* d_in, const int* in_sizes, int n_in,
                              void* d_out, int out_size) {
    const float* x    = (const float*)d_in[0];
    const float* mask = (const float*)d_in[1];
    const float* lnw  = (const float*)d_in[2];
    const float* lnb  = (const float*)d_in[3];
    const float* Wb   = (const float*)d_in[4];
    const float* Wq   = (const float*)d_in[5];
    const float* Wk   = (const float*)d_in[6];
    const float* Wv   = (const float*)d_in[7];
    const float* Wg   = (const float*)d_in[8];
    const float* Wo   = (const float*)d_in[9];
    float* out = (float*)d_out;

    cudaFuncSetAttribute(gemm_tf32_kernel, cudaFuncAttributeMaxDynamicSharedMemorySize, GEMM_SMEM);
    cudaFuncSetAttribute(attn_fa_kernel,   cudaFuncAttributeMaxDynamicSharedMemorySize, ATTN_SMEM);

    ln_bias_kernel<<<NROWS / 8, 256>>>(x, mask, lnw, lnb, Wb);
    gemm_tf32_kernel<<<NROWS / 64, 256, GEMM_SMEM>>>(Wq, Wk, Wv, Wg, Wo, out, 0);
    attn_fa_kernel<<<SS * NH, 256, ATTN_SMEM>>>();
    gemm_tf32_kernel<<<NROWS / 64, 256, GEMM_SMEM>>>(Wq, Wk, Wv, Wg, Wo, out, 1);
}

// round 10
// speedup vs baseline: 1.4241x; 1.0269x over previous
#include <cuda_runtime.h>
#include <cuda_fp16.h>
#include <cstdint>
#include <math.h>

#define SS 256
#define NH 4
#define HD 32
#define DM 128
#define NROWS (SS*SS)   // 65536

// ---------------- scratch (device globals; no runtime alloc allowed) -------
__device__ float g_xn[(size_t)NROWS * DM];   // layernorm output      32MB
__device__ float g_bm[(size_t)NH * NROWS];   // bias+mask [H,S,S]      1MB
__device__ float g_q [(size_t)NROWS * DM];   // [S,H,S,DH]            32MB
__device__ float g_k [(size_t)NROWS * DM];
__device__ float g_v [(size_t)NROWS * DM];
__device__ float g_g [(size_t)NROWS * DM];   // gate proj [S,S,D]
__device__ float g_o [(size_t)NROWS * DM];   // attn out  [S,S,D]

// single extern shared symbol for the whole TU
extern __shared__ char smem_raw[];

__device__ __forceinline__ uint32_t f2tf32(float f) {
    uint32_t u;
    asm("cvt.rna.tf32.f32 %0, %1;" : "=r"(u) : "f"(f));
    return u;
}

// mma.sync m16n8k8 tf32 (sm_80+ PTX; valid on plain compute_103)
__device__ __forceinline__ void mma_tf32(float4& d,
                                         uint32_t a0, uint32_t a1, uint32_t a2, uint32_t a3,
                                         uint32_t b0, uint32_t b1) {
    asm volatile(
        "mma.sync.aligned.m16n8k8.row.col.f32.tf32.tf32.f32 "
        "{%0,%1,%2,%3}, {%4,%5,%6,%7}, {%8,%9}, {%0,%1,%2,%3};"
        : "+f"(d.x), "+f"(d.y), "+f"(d.z), "+f"(d.w)
        : "r"(a0), "r"(a1), "r"(a2), "r"(a3), "r"(b0), "r"(b1));
}

// mma.sync m16n8k16 fp16 with fp32 accumulate
__device__ __forceinline__ void mma_f16(float4& d,
                                        uint32_t a0, uint32_t a1, uint32_t a2, uint32_t a3,
                                        uint32_t b0, uint32_t b1) {
    asm volatile(
        "mma.sync.aligned.m16n8k16.row.col.f32.f16.f16.f32 "
        "{%0,%1,%2,%3}, {%4,%5,%6,%7}, {%8,%9}, {%0,%1,%2,%3};"
        : "+f"(d.x), "+f"(d.y), "+f"(d.z), "+f"(d.w)
        : "r"(a0), "r"(a1), "r"(a2), "r"(a3), "r"(b0), "r"(b1));
}

// pack two floats -> half2 in a b32 reg (lo in low half)
__device__ __forceinline__ uint32_t pack2h(float lo, float hi) {
    uint32_t r;
    asm("cvt.rn.f16x2.f32 %0, %1, %2;" : "=r"(r) : "f"(hi), "f"(lo));
    return r;
}
__device__ __forceinline__ float h2f_rn(float x) {   // fp16 round-trip
    return __half2float(__float2half_rn(x));
}

// ---------------- Kernel A: LayerNorm + (bias projection + mask) -----------
__global__ __launch_bounds__(256)
void ln_bias_kernel(const float* __restrict__ x,
                    const float* __restrict__ mask,
                    const float* __restrict__ lnw,
                    const float* __restrict__ lnb,
                    const float* __restrict__ Wb) {
    int lane = threadIdx.x & 31;
    int row  = blockIdx.x * 8 + (threadIdx.x >> 5);
    const float* xr = x + (size_t)row * DM;

    float v0 = xr[lane], v1 = xr[lane+32], v2 = xr[lane+64], v3 = xr[lane+96];
    float s = v0 + v1 + v2 + v3;
    #pragma unroll
    for (int o = 16; o; o >>= 1) s += __shfl_xor_sync(0xffffffffu, s, o);
    float mu = s * (1.0f/128.0f);
    float d0 = v0-mu, d1 = v1-mu, d2 = v2-mu, d3 = v3-mu;
    float qq = d0*d0 + d1*d1 + d2*d2 + d3*d3;
    #pragma unroll
    for (int o = 16; o; o >>= 1) qq += __shfl_xor_sync(0xffffffffu, qq, o);
    float inv = rsqrtf(qq * (1.0f/128.0f) + 1e-5f);

    float n0 = fmaf(d0*inv, lnw[lane   ], lnb[lane   ]);
    float n1 = fmaf(d1*inv, lnw[lane+32], lnb[lane+32]);
    float n2 = fmaf(d2*inv, lnw[lane+64], lnb[lane+64]);
    float n3 = fmaf(d3*inv, lnw[lane+96], lnb[lane+96]);

    float* xo = g_xn + (size_t)row * DM;
    xo[lane] = n0; xo[lane+32] = n1; xo[lane+64] = n2; xo[lane+96] = n3;

    float mval = mask[row];
    #pragma unroll
    for (int hh = 0; hh < NH; hh++) {
        const float* wb = Wb + hh * DM;
        float dot = n0*wb[lane] + n1*wb[lane+32] + n2*wb[lane+64] + n3*wb[lane+96];
        #pragma unroll
        for (int o = 16; o; o >>= 1) dot += __shfl_xor_sync(0xffffffffu, dot, o);
        if (lane == 0) g_bm[(size_t)hh * NROWS + row] = dot + mval;
    }
}

// ---------------- Kernel B: mma.sync tf32 GEMM, M-tile 64, 2 CTA/SM --------
#define LDA 132
#define GEMM_SMEM ((64 + 128) * LDA * 4)   // 101376 B

__global__ __launch_bounds__(256, 2)
void gemm_tf32_kernel(const float* __restrict__ Wq, const float* __restrict__ Wk,
                      const float* __restrict__ Wv, const float* __restrict__ Wg,
                      const float* __restrict__ Wo, float* __restrict__ out, int mode) {
    uint32_t* As = (uint32_t*)smem_raw;        // [64][LDA] tf32
    uint32_t* Ws = As + 64 * LDA;              // [128][LDA] tf32

    int tid = threadIdx.x, wid = tid >> 5, lane = tid & 31;
    int m0 = blockIdx.x * 64;
    int lr = lane >> 2, lc = lane & 3;
    int wr = wid & 1;          // M chunk of 32 (2 chunks)
    int wc = wid >> 1;         // N chunk of 32 (4 chunks)

    if (mode == 0) {
        #pragma unroll
        for (int t = tid; t < 64 * 32; t += 256) {
            int row = t >> 5, c4 = (t & 31) * 4;
            float4 v = *(const float4*)(g_xn + (size_t)(m0 + row) * DM + c4);
            uint32_t* d = As + row * LDA + c4;
            d[0] = f2tf32(v.x); d[1] = f2tf32(v.y); d[2] = f2tf32(v.z); d[3] = f2tf32(v.w);
        }
    } else {
        #pragma unroll
        for (int t = tid; t < 64 * 32; t += 256) {
            int row = t >> 5, c4 = (t & 31) * 4;
            size_t gi = (size_t)(m0 + row) * DM + c4;
            float4 ov = *(const float4*)(g_o + gi);
            float4 gv = *(const float4*)(g_g + gi);
            uint32_t* d = As + row * LDA + c4;
            d[0] = f2tf32(ov.x / (1.0f + __expf(-gv.x)));
            d[1] = f2tf32(ov.y / (1.0f + __expf(-gv.y)));
            d[2] = f2tf32(ov.z / (1.0f + __expf(-gv.z)));
            d[3] = f2tf32(ov.w / (1.0f + __expf(-gv.w)));
        }
    }

    const float* Wsrc[4] = {Wq, Wk, Wv, Wg};
    int nW = (mode == 0) ? 4 : 1;

    for (int w = 0; w < nW; w++) {
        const float* W = (mode == 1) ? Wo : Wsrc[w];
        #pragma unroll
        for (int t = tid; t < 128 * 32; t += 256) {
            int row = t >> 5, c4 = (t & 31) * 4;
            float4 v = *(const float4*)(W + (size_t)row * DM + c4);
            uint32_t* d = Ws + row * LDA + c4;
            d[0] = f2tf32(v.x); d[1] = f2tf32(v.y); d[2] = f2tf32(v.z); d[3] = f2tf32(v.w);
        }
        __syncthreads();

        float4 acc[2][4];
        #pragma unroll
        for (int mt = 0; mt < 2; mt++)
            #pragma unroll
            for (int nt = 0; nt < 4; nt++) acc[mt][nt] = make_float4(0.f, 0.f, 0.f, 0.f);

        const uint32_t* Ab = As + (wr * 32 + lr) * LDA + lc;
        const uint32_t* Bb = Ws + (wc * 32 + lr) * LDA + lc;

        #pragma unroll
        for (int ks = 0; ks < 16; ks++) {
            int k0 = ks * 8;
            uint32_t a[2][4], b[4][2];
            #pragma unroll
            for (int mt = 0; mt < 2; mt++) {
                const uint32_t* p = Ab + mt * 16 * LDA + k0;
                a[mt][0] = p[0];
                a[mt][1] = p[8 * LDA];
                a[mt][2] = p[4];
                a[mt][3] = p[8 * LDA + 4];
            }
            #pragma unroll
            for (int nt = 0; nt < 4; nt++) {
                const uint32_t* p = Bb + nt * 8 * LDA + k0;
                b[nt][0] = p[0];
                b[nt][1] = p[4];
            }
            #pragma unroll
            for (int mt = 0; mt < 2; mt++)
                #pragma unroll
                for (int nt = 0; nt < 4; nt++)
                    mma_tf32(acc[mt][nt], a[mt][0], a[mt][1], a[mt][2], a[mt][3],
                             b[nt][0], b[nt][1]);
        }

        #pragma unroll
        for (int mt = 0; mt < 2; mt++) {
            int m = m0 + wr * 32 + mt * 16 + lr;
            #pragma unroll
            for (int nt = 0; nt < 4; nt++) {
                int e = wc * 32 + nt * 8 + 2 * lc;
                float2 lo = make_float2(acc[mt][nt].x, acc[mt][nt].y);
                float2 hi = make_float2(acc[mt][nt].z, acc[mt][nt].w);
                if (mode == 1) {
                    *(float2*)(out + (size_t)m * DM + e)       = lo;
                    *(float2*)(out + (size_t)(m + 8) * DM + e) = hi;
                } else if (w == 3) {
                    *(float2*)(g_g + (size_t)m * DM + e)       = lo;
                    *(float2*)(g_g + (size_t)(m + 8) * DM + e) = hi;
                } else {
                    float* dst3 = (w == 0) ? g_q : (w == 1) ? g_k : g_v;
                    int h = e >> 5, dh = e & 31;
                    int b0i = m >> 8, q0i = m & 255;
                    int b1i = (m + 8) >> 8, q1i = (m + 8) & 255;
                    *(float2*)(dst3 + (((size_t)(b0i * NH + h)) * SS + q0i) * HD + dh) = lo;
                    *(float2*)(dst3 + (((size_t)(b1i * NH + h)) * SS + q1i) * HD + dh) = hi;
                }
            }
        }
        __syncthreads();
    }
}

// ---------------- Kernel C: FA2 fp16 attention, 2 CTA/SM -------------------
// QK 2-pass (qh*kh + qh*kl, exp-amplified so compensated); PV 1-pass (ph*vh).
// 8 warps; online softmax over 2 key chunks of 128 -> acc[16] (64 regs)
// smem halves: Kh[256][40], Kl[256][40], Vh^T[32][264]
#define AT_KL 10240
#define AT_VH 20480
#define ATTN_SMEM ((20480 + 8448) * 2)   // 57856 B

__global__ __launch_bounds__(256, 2)
void attn_fa_kernel() {
    __half* sh = (__half*)smem_raw;
    __half* Kh = sh;
    __half* Kl = sh + AT_KL;
    __half* Vh = sh + AT_VH;

    int bh = blockIdx.x, b = bh >> 2, h = bh & 3;
    const float* Qg = g_q + (size_t)bh * (SS * HD);
    const float* Kg = g_k + (size_t)bh * (SS * HD);
    const float* Vg = g_v + (size_t)bh * (SS * HD);

    int tid = threadIdx.x, warp = tid >> 5, lane = tid & 31;
    int lr = lane >> 2, lc = lane & 3;

    // ---- stage K hi/lo [key][dim] (stride 40) and V^T hi [dim][key] (264) --
    for (int i = tid; i < SS * HD; i += 256) {
        int key = i >> 5, d = i & 31;
        float kv = Kg[i];
        __half khv = __float2half_rn(kv);
        Kh[key * 40 + d] = khv;
        Kl[key * 40 + d] = __float2half_rn(kv - __half2float(khv));
        Vh[d * 264 + key] = __float2half_rn(Vg[i]);
    }
    __syncthreads();

    const uint32_t* Khw = (const uint32_t*)Kh;   // word stride 20/row
    const uint32_t* Klw = (const uint32_t*)Kl;
    const uint32_t* Vhw = (const uint32_t*)Vh;   // word stride 132/row

    for (int qt = 0; qt < 2; qt++) {
        int r0 = qt * 128 + warp * 16 + lr;      // rows r0 (.x/.y) and r0+8 (.z/.w)

        // ---- Q fragments (pre-scaled, fp16 hi; 2-pass compensates via Kl) --
        uint32_t qh[2][4];
        #pragma unroll
        for (int t = 0; t < 2; t++) {
            #pragma unroll
            for (int idx = 0; idx < 4; idx++) {
                int row = (idx & 1) ? r0 + 8 : r0;
                int dim = t * 16 + 2 * lc + ((idx >= 2) ? 8 : 0);
                float2 qv = *(const float2*)(Qg + (size_t)row * HD + dim);
                float qx = qv.x * 0.17677669529663687f;
                float qy = qv.y * 0.17677669529663687f;
                qh[t][idx] = pack2h(h2f_rn(qx), h2f_rn(qy));
            }
        }

        const float* bm0 = g_bm + (size_t)h * NROWS + (size_t)r0 * SS;
        const float* bm1 = bm0 + 8 * SS;

        // ---- online-softmax state + output accumulators ----
        float m0r = -3.0e38f, m1r = -3.0e38f, l0 = 0.f, l1 = 0.f;
        float4 oacc[4];
        #pragma unroll
        for (int dn = 0; dn < 4; dn++) oacc[dn] = make_float4(0.f, 0.f, 0.f, 0.f);

        #pragma unroll
        for (int c = 0; c < 2; c++) {
            // ---- S = Q K^T over this 128-key chunk (2-pass: qh*kh + qh*kl) -
            float4 acc[16];
            #pragma unroll
            for (int j = 0; j < 16; j++) acc[j] = make_float4(0.f, 0.f, 0.f, 0.f);

            #pragma unroll
            for (int j = 0; j < 16; j++) {
                int kw = (c * 128 + j * 8 + lr) * 20 + lc;
                uint32_t kh00 = Khw[kw],     kh01 = Khw[kw + 4];
                uint32_t kh10 = Khw[kw + 8], kh11 = Khw[kw + 12];
                uint32_t kl00 = Klw[kw],     kl01 = Klw[kw + 4];
                uint32_t kl10 = Klw[kw + 8], kl11 = Klw[kw + 12];
                mma_f16(acc[j], qh[0][0], qh[0][1], qh[0][2], qh[0][3], kh00, kh01);
                mma_f16(acc[j], qh[1][0], qh[1][1], qh[1][2], qh[1][3], kh10, kh11);
                mma_f16(acc[j], qh[0][0], qh[0][1], qh[0][2], qh[0][3], kl00, kl01);
                mma_f16(acc[j], qh[1][0], qh[1][1], qh[1][2], qh[1][3], kl10, kl11);
            }

            // ---- bias+mask add; chunk max (quad-local) ----
            float cx0 = -3.0e38f, cx1 = -3.0e38f;
            #pragma unroll
            for (int j = 0; j < 16; j++) {
                float2 b0 = *(const float2*)(bm0 + c * 128 + j * 8 + 2 * lc);
                float2 b1 = *(const float2*)(bm1 + c * 128 + j * 8 + 2 * lc);
                acc[j].x += b0.x; acc[j].y += b0.y;
                acc[j].z += b1.x; acc[j].w += b1.y;
                cx0 = fmaxf(cx0, fmaxf(acc[j].x, acc[j].y));
                cx1 = fmaxf(cx1, fmaxf(acc[j].z, acc[j].w));
            }
            cx0 = fmaxf(cx0, __shfl_xor_sync(0xffffffffu, cx0, 1));
            cx0 = fmaxf(cx0, __shfl_xor_sync(0xffffffffu, cx0, 2));
            cx1 = fmaxf(cx1, __shfl_xor_sync(0xffffffffu, cx1, 1));
            cx1 = fmaxf(cx1, __shfl_xor_sync(0xffffffffu, cx1, 2));

            // ---- online rescale ----
            float mn0 = fmaxf(m0r, cx0), mn1 = fmaxf(m1r, cx1);
            float al0 = __expf(m0r - mn0), al1 = __expf(m1r - mn1);
            m0r = mn0; m1r = mn1;
            l0 *= al0; l1 *= al1;
            #pragma unroll
            for (int dn = 0; dn < 4; dn++) {
                oacc[dn].x *= al0; oacc[dn].y *= al0;
                oacc[dn].z *= al1; oacc[dn].w *= al1;
            }

            // ---- exp + partial sums ----
            float s0 = 0.f, s1 = 0.f;
            #pragma unroll
            for (int j = 0; j < 16; j++) {
                acc[j].x = __expf(acc[j].x - mn0); s0 += acc[j].x;
                acc[j].y = __expf(acc[j].y - mn0); s0 += acc[j].y;
                acc[j].z = __expf(acc[j].z - mn1); s1 += acc[j].z;
                acc[j].w = __expf(acc[j].w - mn1); s1 += acc[j].w;
            }
            s0 += __shfl_xor_sync(0xffffffffu, s0, 1);
            s0 += __shfl_xor_sync(0xffffffffu, s0, 2);
            s1 += __shfl_xor_sync(0xffffffffu, s1, 1);
            s1 += __shfl_xor_sync(0xffffffffu, s1, 2);
            l0 += s0; l1 += s1;

            // ---- O += P V over chunk (1-pass: ph*vh) ----
            #pragma unroll
            for (int t = 0; t < 8; t++) {
                float4 c0 = acc[2 * t], c1 = acc[2 * t + 1];
                uint32_t ah0 = pack2h(h2f_rn(c0.x), h2f_rn(c0.y));
                uint32_t ah1 = pack2h(h2f_rn(c0.z), h2f_rn(c0.w));
                uint32_t ah2 = pack2h(h2f_rn(c1.x), h2f_rn(c1.y));
                uint32_t ah3 = pack2h(h2f_rn(c1.z), h2f_rn(c1.w));
                #pragma unroll
                for (int dn = 0; dn < 4; dn++) {
                    int vw = (dn * 8 + lr) * 132 + c * 64 + 8 * t + lc;
                    mma_f16(oacc[dn], ah0, ah1, ah2, ah3, Vhw[vw], Vhw[vw + 4]);
                }
            }
        }

        // ---- normalize + store ----
        float i0 = 1.0f / l0, i1 = 1.0f / l1;
        float* o0 = g_o + ((size_t)(b * 256 + r0) * NH + h) * HD;
        float* o1 = g_o + ((size_t)(b * 256 + r0 + 8) * NH + h) * HD;
        #pragma unroll
        for (int dn = 0; dn < 4; dn++) {
            *(float2*)(o0 + dn * 8 + 2 * lc) = make_float2(oacc[dn].x * i0, oacc[dn].y * i0);
            *(float2*)(o1 + dn * 8 + 2 * lc) = make_float2(oacc[dn].z * i1, oacc[dn].w * i1);
        }
    }
}

// ---------------- launch ----------------------------------------------------
extern "C" void kernel_launch(void* const* d_in, const int* in_sizes, int n_in,
                              void* d_out, int out_size) {
    const float* x    = (const float*)d_in[0];
    const float* mask = (const float*)d_in[1];
    const float* lnw  = (const float*)d_in[2];
    const float* lnb  = (const float*)d_in[3];
    const float* Wb   = (const float*)d_in[4];
    const float* Wq   = (const float*)d_in[5];
    const float* Wk   = (const float*)d_in[6];
    const float* Wv   = (const float*)d_in[7];
    const float* Wg   = (const float*)d_in[8];
    const float* Wo   = (const float*)d_in[9];
    float* out = (float*)d_out;

    cudaFuncSetAttribute(gemm_tf32_kernel, cudaFuncAttributeMaxDynamicSharedMemorySize, GEMM_SMEM);
    cudaFuncSetAttribute(attn_fa_kernel,   cudaFuncAttributeMaxDynamicSharedMemorySize, ATTN_SMEM);

    ln_bias_kernel<<<NROWS / 8, 256>>>(x, mask, lnw, lnb, Wb);
    gemm_tf32_kernel<<<NROWS / 64, 256, GEMM_SMEM>>>(Wq, Wk, Wv, Wg, Wo, out, 0);
    attn_fa_kernel<<<SS * NH, 256, ATTN_SMEM>>>();
    gemm_tf32_kernel<<<NROWS / 64, 256, GEMM_SMEM>>>(Wq, Wk, Wv, Wg, Wo, out, 1);
}

// round 11
// speedup vs baseline: 1.4243x; 1.0001x over previous
#include <cuda_runtime.h>
#include <cuda_fp16.h>
#include <cstdint>
#include <math.h>

#define SS 256
#define NH 4
#define HD 32
#define DM 128
#define NROWS (SS*SS)   // 65536

// ---------------- scratch (device globals; no runtime alloc allowed) -------
__device__ float g_xn[(size_t)NROWS * DM];   // layernorm output      32MB
__device__ float g_bm[(size_t)NH * NROWS];   // bias+mask [H,S,S]      1MB
__device__ float g_q [(size_t)NROWS * DM];   // [S,H,S,DH]            32MB
__device__ float g_k [(size_t)NROWS * DM];
__device__ float g_v [(size_t)NROWS * DM];
__device__ float g_g [(size_t)NROWS * DM];   // gate proj [S,S,D]
__device__ float g_o [(size_t)NROWS * DM];   // attn out  [S,S,D]

// single extern shared symbol for the whole TU
extern __shared__ char smem_raw[];

__device__ __forceinline__ uint32_t f2tf32(float f) {
    uint32_t u;
    asm("cvt.rna.tf32.f32 %0, %1;" : "=r"(u) : "f"(f));
    return u;
}

// mma.sync m16n8k8 tf32 (sm_80+ PTX; valid on plain compute_103)
__device__ __forceinline__ void mma_tf32(float4& d,
                                         uint32_t a0, uint32_t a1, uint32_t a2, uint32_t a3,
                                         uint32_t b0, uint32_t b1) {
    asm volatile(
        "mma.sync.aligned.m16n8k8.row.col.f32.tf32.tf32.f32 "
        "{%0,%1,%2,%3}, {%4,%5,%6,%7}, {%8,%9}, {%0,%1,%2,%3};"
        : "+f"(d.x), "+f"(d.y), "+f"(d.z), "+f"(d.w)
        : "r"(a0), "r"(a1), "r"(a2), "r"(a3), "r"(b0), "r"(b1));
}

// mma.sync m16n8k16 fp16 with fp32 accumulate
__device__ __forceinline__ void mma_f16(float4& d,
                                        uint32_t a0, uint32_t a1, uint32_t a2, uint32_t a3,
                                        uint32_t b0, uint32_t b1) {
    asm volatile(
        "mma.sync.aligned.m16n8k16.row.col.f32.f16.f16.f32 "
        "{%0,%1,%2,%3}, {%4,%5,%6,%7}, {%8,%9}, {%0,%1,%2,%3};"
        : "+f"(d.x), "+f"(d.y), "+f"(d.z), "+f"(d.w)
        : "r"(a0), "r"(a1), "r"(a2), "r"(a3), "r"(b0), "r"(b1));
}

// pack two floats -> half2 in a b32 reg (lo in low half)
__device__ __forceinline__ uint32_t pack2h(float lo, float hi) {
    uint32_t r;
    asm("cvt.rn.f16x2.f32 %0, %1, %2;" : "=r"(r) : "f"(hi), "f"(lo));
    return r;
}
__device__ __forceinline__ float h2f_rn(float x) {   // fp16 round-trip
    return __half2float(__float2half_rn(x));
}

// ---------------- Kernel A: LayerNorm + (bias projection + mask) -----------
__global__ __launch_bounds__(256)
void ln_bias_kernel(const float* __restrict__ x,
                    const float* __restrict__ mask,
                    const float* __restrict__ lnw,
                    const float* __restrict__ lnb,
                    const float* __restrict__ Wb) {
    int lane = threadIdx.x & 31;
    int row  = blockIdx.x * 8 + (threadIdx.x >> 5);
    const float* xr = x + (size_t)row * DM;

    float v0 = xr[lane], v1 = xr[lane+32], v2 = xr[lane+64], v3 = xr[lane+96];
    float s = v0 + v1 + v2 + v3;
    #pragma unroll
    for (int o = 16; o; o >>= 1) s += __shfl_xor_sync(0xffffffffu, s, o);
    float mu = s * (1.0f/128.0f);
    float d0 = v0-mu, d1 = v1-mu, d2 = v2-mu, d3 = v3-mu;
    float qq = d0*d0 + d1*d1 + d2*d2 + d3*d3;
    #pragma unroll
    for (int o = 16; o; o >>= 1) qq += __shfl_xor_sync(0xffffffffu, qq, o);
    float inv = rsqrtf(qq * (1.0f/128.0f) + 1e-5f);

    float n0 = fmaf(d0*inv, lnw[lane   ], lnb[lane   ]);
    float n1 = fmaf(d1*inv, lnw[lane+32], lnb[lane+32]);
    float n2 = fmaf(d2*inv, lnw[lane+64], lnb[lane+64]);
    float n3 = fmaf(d3*inv, lnw[lane+96], lnb[lane+96]);

    float* xo = g_xn + (size_t)row * DM;
    xo[lane] = n0; xo[lane+32] = n1; xo[lane+64] = n2; xo[lane+96] = n3;

    float mval = mask[row];
    #pragma unroll
    for (int hh = 0; hh < NH; hh++) {
        const float* wb = Wb + hh * DM;
        float dot = n0*wb[lane] + n1*wb[lane+32] + n2*wb[lane+64] + n3*wb[lane+96];
        #pragma unroll
        for (int o = 16; o; o >>= 1) dot += __shfl_xor_sync(0xffffffffu, dot, o);
        if (lane == 0) g_bm[(size_t)hh * NROWS + row] = dot + mval;
    }
}

// ---------------- Kernel B: mma.sync tf32 GEMM, M-tile 64, 2 CTA/SM --------
#define LDA 132
#define GEMM_SMEM ((64 + 128) * LDA * 4)   // 101376 B

__global__ __launch_bounds__(256, 2)
void gemm_tf32_kernel(const float* __restrict__ Wq, const float* __restrict__ Wk,
                      const float* __restrict__ Wv, const float* __restrict__ Wg,
                      const float* __restrict__ Wo, float* __restrict__ out, int mode) {
    uint32_t* As = (uint32_t*)smem_raw;        // [64][LDA] tf32
    uint32_t* Ws = As + 64 * LDA;              // [128][LDA] tf32

    int tid = threadIdx.x, wid = tid >> 5, lane = tid & 31;
    int m0 = blockIdx.x * 64;
    int lr = lane >> 2, lc = lane & 3;
    int wr = wid & 1;          // M chunk of 32 (2 chunks)
    int wc = wid >> 1;         // N chunk of 32 (4 chunks)

    if (mode == 0) {
        #pragma unroll
        for (int t = tid; t < 64 * 32; t += 256) {
            int row = t >> 5, c4 = (t & 31) * 4;
            float4 v = *(const float4*)(g_xn + (size_t)(m0 + row) * DM + c4);
            uint32_t* d = As + row * LDA + c4;
            d[0] = f2tf32(v.x); d[1] = f2tf32(v.y); d[2] = f2tf32(v.z); d[3] = f2tf32(v.w);
        }
    } else {
        #pragma unroll
        for (int t = tid; t < 64 * 32; t += 256) {
            int row = t >> 5, c4 = (t & 31) * 4;
            size_t gi = (size_t)(m0 + row) * DM + c4;
            float4 ov = *(const float4*)(g_o + gi);
            float4 gv = *(const float4*)(g_g + gi);
            uint32_t* d = As + row * LDA + c4;
            d[0] = f2tf32(ov.x / (1.0f + __expf(-gv.x)));
            d[1] = f2tf32(ov.y / (1.0f + __expf(-gv.y)));
            d[2] = f2tf32(ov.z / (1.0f + __expf(-gv.z)));
            d[3] = f2tf32(ov.w / (1.0f + __expf(-gv.w)));
        }
    }

    const float* Wsrc[4] = {Wq, Wk, Wv, Wg};
    int nW = (mode == 0) ? 4 : 1;

    for (int w = 0; w < nW; w++) {
        const float* W = (mode == 1) ? Wo : Wsrc[w];
        #pragma unroll
        for (int t = tid; t < 128 * 32; t += 256) {
            int row = t >> 5, c4 = (t & 31) * 4;
            float4 v = *(const float4*)(W + (size_t)row * DM + c4);
            uint32_t* d = Ws + row * LDA + c4;
            d[0] = f2tf32(v.x); d[1] = f2tf32(v.y); d[2] = f2tf32(v.z); d[3] = f2tf32(v.w);
        }
        __syncthreads();

        float4 acc[2][4];
        #pragma unroll
        for (int mt = 0; mt < 2; mt++)
            #pragma unroll
            for (int nt = 0; nt < 4; nt++) acc[mt][nt] = make_float4(0.f, 0.f, 0.f, 0.f);

        const uint32_t* Ab = As + (wr * 32 + lr) * LDA + lc;
        const uint32_t* Bb = Ws + (wc * 32 + lr) * LDA + lc;

        #pragma unroll
        for (int ks = 0; ks < 16; ks++) {
            int k0 = ks * 8;
            uint32_t a[2][4], b[4][2];
            #pragma unroll
            for (int mt = 0; mt < 2; mt++) {
                const uint32_t* p = Ab + mt * 16 * LDA + k0;
                a[mt][0] = p[0];
                a[mt][1] = p[8 * LDA];
                a[mt][2] = p[4];
                a[mt][3] = p[8 * LDA + 4];
            }
            #pragma unroll
            for (int nt = 0; nt < 4; nt++) {
                const uint32_t* p = Bb + nt * 8 * LDA + k0;
                b[nt][0] = p[0];
                b[nt][1] = p[4];
            }
            #pragma unroll
            for (int mt = 0; mt < 2; mt++)
                #pragma unroll
                for (int nt = 0; nt < 4; nt++)
                    mma_tf32(acc[mt][nt], a[mt][0], a[mt][1], a[mt][2], a[mt][3],
                             b[nt][0], b[nt][1]);
        }

        #pragma unroll
        for (int mt = 0; mt < 2; mt++) {
            int m = m0 + wr * 32 + mt * 16 + lr;
            #pragma unroll
            for (int nt = 0; nt < 4; nt++) {
                int e = wc * 32 + nt * 8 + 2 * lc;
                float2 lo = make_float2(acc[mt][nt].x, acc[mt][nt].y);
                float2 hi = make_float2(acc[mt][nt].z, acc[mt][nt].w);
                if (mode == 1) {
                    *(float2*)(out + (size_t)m * DM + e)       = lo;
                    *(float2*)(out + (size_t)(m + 8) * DM + e) = hi;
                } else if (w == 3) {
                    *(float2*)(g_g + (size_t)m * DM + e)       = lo;
                    *(float2*)(g_g + (size_t)(m + 8) * DM + e) = hi;
                } else {
                    float* dst3 = (w == 0) ? g_q : (w == 1) ? g_k : g_v;
                    int h = e >> 5, dh = e & 31;
                    int b0i = m >> 8, q0i = m & 255;
                    int b1i = (m + 8) >> 8, q1i = (m + 8) & 255;
                    *(float2*)(dst3 + (((size_t)(b0i * NH + h)) * SS + q0i) * HD + dh) = lo;
                    *(float2*)(dst3 + (((size_t)(b1i * NH + h)) * SS + q1i) * HD + dh) = hi;
                }
            }
        }
        __syncthreads();
    }
}

// ---------------- Kernel C: FA2 fp16 attention, 2 CTA/SM -------------------
// QK 2-pass (qh*kh + qh*kl, exp-amplified so compensated); PV 1-pass (ph*vh).
// 8 warps; online softmax over 2 key chunks of 128 -> acc[16] (64 regs)
// smem halves: Kh[256][40], Kl[256][40], Vh^T[32][264]
#define AT_KL 10240
#define AT_VH 20480
#define ATTN_SMEM ((20480 + 8448) * 2)   // 57856 B

__global__ __launch_bounds__(256, 2)
void attn_fa_kernel() {
    __half* sh = (__half*)smem_raw;
    __half* Kh = sh;
    __half* Kl = sh + AT_KL;
    __half* Vh = sh + AT_VH;

    int bh = blockIdx.x, b = bh >> 2, h = bh & 3;
    const float* Qg = g_q + (size_t)bh * (SS * HD);
    const float* Kg = g_k + (size_t)bh * (SS * HD);
    const float* Vg = g_v + (size_t)bh * (SS * HD);

    int tid = threadIdx.x, warp = tid >> 5, lane = tid & 31;
    int lr = lane >> 2, lc = lane & 3;

    // ---- stage K hi/lo [key][dim] (stride 40) and V^T hi [dim][key] (264) --
    for (int i = tid; i < SS * HD; i += 256) {
        int key = i >> 5, d = i & 31;
        float kv = Kg[i];
        __half khv = __float2half_rn(kv);
        Kh[key * 40 + d] = khv;
        Kl[key * 40 + d] = __float2half_rn(kv - __half2float(khv));
        Vh[d * 264 + key] = __float2half_rn(Vg[i]);
    }
    __syncthreads();

    const uint32_t* Khw = (const uint32_t*)Kh;   // word stride 20/row
    const uint32_t* Klw = (const uint32_t*)Kl;
    const uint32_t* Vhw = (const uint32_t*)Vh;   // word stride 132/row

    for (int qt = 0; qt < 2; qt++) {
        int r0 = qt * 128 + warp * 16 + lr;      // rows r0 (.x/.y) and r0+8 (.z/.w)

        // ---- Q fragments (pre-scaled, fp16 hi; 2-pass compensates via Kl) --
        uint32_t qh[2][4];
        #pragma unroll
        for (int t = 0; t < 2; t++) {
            #pragma unroll
            for (int idx = 0; idx < 4; idx++) {
                int row = (idx & 1) ? r0 + 8 : r0;
                int dim = t * 16 + 2 * lc + ((idx >= 2) ? 8 : 0);
                float2 qv = *(const float2*)(Qg + (size_t)row * HD + dim);
                float qx = qv.x * 0.17677669529663687f;
                float qy = qv.y * 0.17677669529663687f;
                qh[t][idx] = pack2h(h2f_rn(qx), h2f_rn(qy));
            }
        }

        const float* bm0 = g_bm + (size_t)h * NROWS + (size_t)r0 * SS;
        const float* bm1 = bm0 + 8 * SS;

        // ---- online-softmax state + output accumulators ----
        float m0r = -3.0e38f, m1r = -3.0e38f, l0 = 0.f, l1 = 0.f;
        float4 oacc[4];
        #pragma unroll
        for (int dn = 0; dn < 4; dn++) oacc[dn] = make_float4(0.f, 0.f, 0.f, 0.f);

        #pragma unroll
        for (int c = 0; c < 2; c++) {
            // ---- S = Q K^T over this 128-key chunk (2-pass: qh*kh + qh*kl) -
            float4 acc[16];
            #pragma unroll
            for (int j = 0; j < 16; j++) acc[j] = make_float4(0.f, 0.f, 0.f, 0.f);

            #pragma unroll
            for (int j = 0; j < 16; j++) {
                int kw = (c * 128 + j * 8 + lr) * 20 + lc;
                uint32_t kh00 = Khw[kw],     kh01 = Khw[kw + 4];
                uint32_t kh10 = Khw[kw + 8], kh11 = Khw[kw + 12];
                uint32_t kl00 = Klw[kw],     kl01 = Klw[kw + 4];
                uint32_t kl10 = Klw[kw + 8], kl11 = Klw[kw + 12];
                mma_f16(acc[j], qh[0][0], qh[0][1], qh[0][2], qh[0][3], kh00, kh01);
                mma_f16(acc[j], qh[1][0], qh[1][1], qh[1][2], qh[1][3], kh10, kh11);
                mma_f16(acc[j], qh[0][0], qh[0][1], qh[0][2], qh[0][3], kl00, kl01);
                mma_f16(acc[j], qh[1][0], qh[1][1], qh[1][2], qh[1][3], kl10, kl11);
            }

            // ---- bias+mask add; chunk max (quad-local) ----
            float cx0 = -3.0e38f, cx1 = -3.0e38f;
            #pragma unroll
            for (int j = 0; j < 16; j++) {
                float2 b0 = *(const float2*)(bm0 + c * 128 + j * 8 + 2 * lc);
                float2 b1 = *(const float2*)(bm1 + c * 128 + j * 8 + 2 * lc);
                acc[j].x += b0.x; acc[j].y += b0.y;
                acc[j].z += b1.x; acc[j].w += b1.y;
                cx0 = fmaxf(cx0, fmaxf(acc[j].x, acc[j].y));
                cx1 = fmaxf(cx1, fmaxf(acc[j].z, acc[j].w));
            }
            cx0 = fmaxf(cx0, __shfl_xor_sync(0xffffffffu, cx0, 1));
            cx0 = fmaxf(cx0, __shfl_xor_sync(0xffffffffu, cx0, 2));
            cx1 = fmaxf(cx1, __shfl_xor_sync(0xffffffffu, cx1, 1));
            cx1 = fmaxf(cx1, __shfl_xor_sync(0xffffffffu, cx1, 2));

            // ---- online rescale ----
            float mn0 = fmaxf(m0r, cx0), mn1 = fmaxf(m1r, cx1);
            float al0 = __expf(m0r - mn0), al1 = __expf(m1r - mn1);
            m0r = mn0; m1r = mn1;
            l0 *= al0; l1 *= al1;
            #pragma unroll
            for (int dn = 0; dn < 4; dn++) {
                oacc[dn].x *= al0; oacc[dn].y *= al0;
                oacc[dn].z *= al1; oacc[dn].w *= al1;
            }

            // ---- exp + partial sums ----
            float s0 = 0.f, s1 = 0.f;
            #pragma unroll
            for (int j = 0; j < 16; j++) {
                acc[j].x = __expf(acc[j].x - mn0); s0 += acc[j].x;
                acc[j].y = __expf(acc[j].y - mn0); s0 += acc[j].y;
                acc[j].z = __expf(acc[j].z - mn1); s1 += acc[j].z;
                acc[j].w = __expf(acc[j].w - mn1); s1 += acc[j].w;
            }
            s0 += __shfl_xor_sync(0xffffffffu, s0, 1);
            s0 += __shfl_xor_sync(0xffffffffu, s0, 2);
            s1 += __shfl_xor_sync(0xffffffffu, s1, 1);
            s1 += __shfl_xor_sync(0xffffffffu, s1, 2);
            l0 += s0; l1 += s1;

            // ---- O += P V over chunk (1-pass: ph*vh) ----
            #pragma unroll
            for (int t = 0; t < 8; t++) {
                float4 c0 = acc[2 * t], c1 = acc[2 * t + 1];
                uint32_t ah0 = pack2h(h2f_rn(c0.x), h2f_rn(c0.y));
                uint32_t ah1 = pack2h(h2f_rn(c0.z), h2f_rn(c0.w));
                uint32_t ah2 = pack2h(h2f_rn(c1.x), h2f_rn(c1.y));
                uint32_t ah3 = pack2h(h2f_rn(c1.z), h2f_rn(c1.w));
                #pragma unroll
                for (int dn = 0; dn < 4; dn++) {
                    int vw = (dn * 8 + lr) * 132 + c * 64 + 8 * t + lc;
                    mma_f16(oacc[dn], ah0, ah1, ah2, ah3, Vhw[vw], Vhw[vw + 4]);
                }
            }
        }

        // ---- normalize + store ----
        float i0 = 1.0f / l0, i1 = 1.0f / l1;
        float* o0 = g_o + ((size_t)(b * 256 + r0) * NH + h) * HD;
        float* o1 = g_o + ((size_t)(b * 256 + r0 + 8) * NH + h) * HD;
        #pragma unroll
        for (int dn = 0; dn < 4; dn++) {
            *(float2*)(o0 + dn * 8 + 2 * lc) = make_float2(oacc[dn].x * i0, oacc[dn].y * i0);
            *(float2*)(o1 + dn * 8 + 2 * lc) = make_float2(oacc[dn].z * i1, oacc[dn].w * i1);
        }
    }
}

// ---------------- launch ----------------------------------------------------
extern "C" void kernel_launch(void* const* d_in, const int* in_sizes, int n_in,
                              void* d_out, int out_size) {
    const float* x    = (const float*)d_in[0];
    const float* mask = (const float*)d_in[1];
    const float* lnw  = (const float*)d_in[2];
    const float* lnb  = (const float*)d_in[3];
    const float* Wb   = (const float*)d_in[4];
    const float* Wq   = (const float*)d_in[5];
    const float* Wk   = (const float*)d_in[6];
    const float* Wv   = (const float*)d_in[7];
    const float* Wg   = (const float*)d_in[8];
    const float* Wo   = (const float*)d_in[9];
    float* out = (float*)d_out;

    cudaFuncSetAttribute(gemm_tf32_kernel, cudaFuncAttributeMaxDynamicSharedMemorySize, GEMM_SMEM);
    cudaFuncSetAttribute(attn_fa_kernel,   cudaFuncAttributeMaxDynamicSharedMemorySize, ATTN_SMEM);

    ln_bias_kernel<<<NROWS / 8, 256>>>(x, mask, lnw, lnb, Wb);
    gemm_tf32_kernel<<<NROWS / 64, 256, GEMM_SMEM>>>(Wq, Wk, Wv, Wg, Wo, out, 0);
    attn_fa_kernel<<<SS * NH, 256, ATTN_SMEM>>>();
    gemm_tf32_kernel<<<NROWS / 64, 256, GEMM_SMEM>>>(Wq, Wk, Wv, Wg, Wo, out, 1);
}